// round 9
// baseline (speedup 1.0000x reference)
#include <cuda_runtime.h>
#include <cuda_fp16.h>
#include <cstdint>
#include <math.h>

// ---------------------------------------------------------------------------
// QAttention round 9: fp16 HMMA conv at N=256 (512-thread CTA, 16 warps/SM),
// merged prep kernels (7 launches total), conv in profiled slot.
// ---------------------------------------------------------------------------

#define SPATIAL 16384
typedef unsigned long long u64;

// ------------------------- mma.sync helpers --------------------------------
__device__ __forceinline__ uint32_t smem_to_u32(const void* p) {
    uint32_t a;
    asm("{ .reg .u64 t; cvta.to.shared.u64 t, %1; cvt.u32.u64 %0, t; }"
        : "=r"(a) : "l"(p));
    return a;
}
__device__ __forceinline__ void ldsm4(uint32_t* r, uint32_t addr) {
    asm volatile("ldmatrix.sync.aligned.m8n8.x4.shared.b16 {%0,%1,%2,%3}, [%4];"
                 : "=r"(r[0]), "=r"(r[1]), "=r"(r[2]), "=r"(r[3]) : "r"(addr));
}
__device__ __forceinline__ void mma_f16(float* d, const uint32_t* a,
                                        const uint32_t* b) {
    asm volatile(
        "mma.sync.aligned.m16n8k16.row.col.f32.f16.f16.f32 "
        "{%0,%1,%2,%3}, {%4,%5,%6,%7}, {%8,%9}, {%0,%1,%2,%3};"
        : "+f"(d[0]), "+f"(d[1]), "+f"(d[2]), "+f"(d[3])
        : "r"(a[0]), "r"(a[1]), "r"(a[2]), "r"(a[3]), "r"(b[0]), "r"(b[1]));
}
__device__ __forceinline__ uint32_t sw_addr(uint32_t base, int row, int unit) {
    return base + row * 128 + (((unit) ^ (row & 7)) << 4);
}
__device__ __forceinline__ void cp_async16(uint32_t saddr, const void* gptr,
                                           uint32_t bytes) {
    asm volatile("cp.async.cg.shared.global [%0], [%1], 16, %2;"
                 :: "r"(saddr), "l"(gptr), "r"(bytes) : "memory");
}
#define CP_COMMIT() asm volatile("cp.async.commit_group;" ::: "memory")
#define CP_WAIT1()  asm volatile("cp.async.wait_group 1;" ::: "memory")
#define CP_WAIT0()  asm volatile("cp.async.wait_group 0;" ::: "memory")

// ------------------------- f32x2 helpers (final_gemm) ----------------------
__device__ __forceinline__ u64 pack2(float lo, float hi) {
    u64 r; asm("mov.b64 %0,{%1,%2};" : "=l"(r) : "f"(lo), "f"(hi)); return r;
}
__device__ __forceinline__ float2 unpack2(u64 v) {
    float2 f; asm("mov.b64 {%0,%1},%2;" : "=f"(f.x), "=f"(f.y) : "l"(v)); return f;
}
__device__ __forceinline__ u64 fma2(u64 a, u64 b, u64 c) {
    u64 d; asm("fma.rn.f32x2 %0,%1,%2,%3;" : "=l"(d) : "l"(a), "l"(b), "l"(c)); return d;
}

// ------------------------- device scratch ----------------------------------
__device__ float g_Wqkv[384 * 128];
__device__ float g_Wdw[384 * 384 * 9];
__device__ float g_Wpo[128 * 128];
__device__ __half g_Weff16[384 * 1152];          // [o][tap*128+c]
__device__ float g_tb[384 * 9];
__device__ __half g_xt16[2 * SPATIAL * 128];     // [b][s][c]
__device__ float g_qkv2[2 * 384 * SPATIAL];
__device__ float g_attnP[2 * 4 * 32 * 32];
__device__ float g_ss[2 * 256];
__device__ float g_M2[2 * 128 * 128];

// ---------------------------------------------------------------------------
// P1: all three Hamilton expansions in one kernel.
// ---------------------------------------------------------------------------
__device__ __forceinline__ void ham_one(const float* r, const float* i_,
                                        const float* j_, const float* k_,
                                        float* dst, int idx,
                                        int O4, int C4, int T) {
    int tap = idx % T;
    int rem = idx / T;
    int C = 4 * C4;
    int c = rem % C;
    int o = rem / C;
    int br = o / O4, oo = o % O4;
    int bc = c / C4, cc = c % C4;

    const int   src[16] = {0,1,2,3, 1,0,3,2, 2,3,0,1, 3,2,1,0};
    const float sgn[16] = {1.f,-1.f,-1.f,-1.f, 1.f,1.f,-1.f,1.f,
                           1.f,1.f,1.f,-1.f,  1.f,-1.f,1.f,1.f};
    const float* comp[4] = {r, i_, j_, k_};
    dst[idx] = sgn[br * 4 + bc] * comp[src[br * 4 + bc]][(oo * C4 + cc) * T + tap];
}

#define N_QKV (384 * 128)
#define N_DW  (384 * 384 * 9)
#define N_PO  (128 * 128)

__global__ void expand_all(const float* __restrict__ qr, const float* __restrict__ qi,
                           const float* __restrict__ qj, const float* __restrict__ qk,
                           const float* __restrict__ dr, const float* __restrict__ di,
                           const float* __restrict__ dj, const float* __restrict__ dk,
                           const float* __restrict__ pr, const float* __restrict__ pi,
                           const float* __restrict__ pj, const float* __restrict__ pk) {
    int idx = blockIdx.x * 256 + threadIdx.x;
    if (idx < N_QKV) {
        ham_one(qr, qi, qj, qk, g_Wqkv, idx, 96, 32, 1);
    } else if (idx < N_QKV + N_DW) {
        ham_one(dr, di, dj, dk, g_Wdw, idx - N_QKV, 96, 96, 9);
    } else if (idx < N_QKV + N_DW + N_PO) {
        ham_one(pr, pi, pj, pk, g_Wpo, idx - N_QKV - N_DW, 32, 32, 1);
    }
}

// ---------------------------------------------------------------------------
// P2: Weff per output row -> fp16 at [o][tap*128+c]; tb fold.
// ---------------------------------------------------------------------------
__global__ __launch_bounds__(128)
void weff_o(const float* __restrict__ qkv_b) {
    int o = blockIdx.x;
    int c = threadIdx.x;

    __shared__ float wdw_s[288 + 8];
    __shared__ float wq_s[32 * 128];
    __shared__ float qb_s[384];

    for (int m = c; m < 384; m += 128) qb_s[m] = qkv_b[m];

    float acc[9], tbp[9];
#pragma unroll
    for (int t = 0; t < 9; ++t) { acc[t] = 0.f; tbp[t] = 0.f; }

    const float* wdw_row = g_Wdw + (size_t)o * 3456;

    for (int cb = 0; cb < 12; ++cb) {
        __syncthreads();
        for (int i = c; i < 288; i += 128)
            wdw_s[i] = wdw_row[cb * 288 + i];
        for (int i = c; i < 4096; i += 128) {
            int m = i >> 7, col = i & 127;
            wq_s[m * 128 + col] = g_Wqkv[(cb * 32 + m) * 128 + col];
        }
        __syncthreads();
#pragma unroll 4
        for (int m = 0; m < 32; ++m) {
            float wq = wq_s[m * 128 + c];
#pragma unroll
            for (int t = 0; t < 9; ++t)
                acc[t] = fmaf(wdw_s[m * 9 + t], wq, acc[t]);
        }
        if (c < 32) {
            float qb = qb_s[cb * 32 + c];
#pragma unroll
            for (int t = 0; t < 9; ++t)
                tbp[t] = fmaf(wdw_s[c * 9 + t], qb, tbp[t]);
        }
    }

#pragma unroll
    for (int t = 0; t < 9; ++t)
        g_Weff16[(size_t)o * 1152 + t * 128 + c] = __float2half(acc[t]);

    if (c < 32) {
#pragma unroll
        for (int t = 0; t < 9; ++t) {
            float v = tbp[t];
#pragma unroll
            for (int off = 16; off; off >>= 1)
                v += __shfl_xor_sync(0xffffffffu, v, off);
            if (c == 0) g_tb[o * 9 + t] = v;
        }
    }
}

// ---------------------------------------------------------------------------
// P3: transpose x to [b][s][c] fp16; block(0,0) also zeros scratch.
// ---------------------------------------------------------------------------
__global__ void prep_x(const float* __restrict__ X) {
    __shared__ float t[128][33];
    int s0 = blockIdx.x * 32;
    int b  = blockIdx.y;
    int tid = threadIdx.x;

    if (blockIdx.x == 0 && b == 0) {
        for (int i = tid; i < 8192; i += 256) g_attnP[i] = 0.f;
        for (int i = tid; i < 512; i += 256) g_ss[i] = 0.f;
    }
    for (int i = tid; i < 4096; i += 256) {
        int c = i >> 5, s = i & 31;
        t[c][s] = X[((size_t)(b * 128 + c)) * SPATIAL + s0 + s];
    }
    __syncthreads();
    for (int i = tid; i < 4096; i += 256) {
        int s = i >> 7, c = i & 127;
        g_xt16[((size_t)b * SPATIAL + s0 + s) * 128 + c] = __float2half(t[c][s]);
    }
}

// ---------------------------------------------------------------------------
// P4: conv via mma.sync fp16, N=256 (2 rows), 512 threads (16 warps 2Mx8N).
// K: 9 taps x 2 chunks of 64 ch = 18 iterations x 4 k16-steps.
// Stage: A [128][64] 16KB + B [256][64] 32KB = 48KB; x2 = 96KB.
// ---------------------------------------------------------------------------
#define ST_A 0
#define ST_B (16 * 1024)
#define STAGE_BYTES (48 * 1024)
#define CONV_SMEM (2 * STAGE_BYTES)

__device__ __forceinline__ void conv_fill(uint32_t sbase, int tid,
                                          int it, int y0, int o0, int b) {
    int tap = it >> 1;
    int ch  = (it & 1) * 64;
    int dy = tap / 3 - 1, dx = tap % 3 - 1;
    uint32_t stg = sbase + (it & 1) * STAGE_BYTES;

    // A: [128 o][64 k] = 1024 x 16B
    for (int i = tid; i < 1024; i += 512) {
        int row = i >> 3, u = i & 7;
        const __half* src = g_Weff16 +
            (size_t)(o0 + row) * 1152 + tap * 128 + ch + u * 8;
        cp_async16(sw_addr(stg + ST_A, row, u), src, 16u);
    }
    // B: [256 n][64 k] = 2048 x 16B, (dy,dx)-gathered, zero halo
    for (int i = tid; i < 2048; i += 512) {
        int n = i >> 3, u = i & 7;
        int yy = y0 + (n >> 7) + dy;
        int xx = (n & 127) + dx;
        bool ok = ((unsigned)yy < 128u) && ((unsigned)xx < 128u);
        const __half* src = ok
            ? g_xt16 + ((size_t)b * SPATIAL + yy * 128 + xx) * 128 + ch + u * 8
            : g_xt16;
        cp_async16(sw_addr(stg + ST_B, n, u), src, ok ? 16u : 0u);
    }
    CP_COMMIT();
}

__global__ __launch_bounds__(512)
void conv_mma(const float* __restrict__ dwb) {
    extern __shared__ char smem[];
    uint32_t sbase = smem_to_u32(smem);
    int tid = threadIdx.x, wid = tid >> 5, lane = tid & 31;
    int y0 = blockIdx.x * 2;      // two image rows
    int o0 = blockIdx.y * 128;    // output-channel tile
    int b  = blockIdx.z;

    int warpM = wid >> 3;         // 0..1 -> 64 chans
    int warpN = wid & 7;          // 0..7 -> 32 pixels each
    int lm = lane >> 3;
    int r8 = lane & 7;

    float acc[4][4][4];
#pragma unroll
    for (int mt = 0; mt < 4; ++mt)
#pragma unroll
        for (int nt = 0; nt < 4; ++nt)
#pragma unroll
            for (int q = 0; q < 4; ++q) acc[mt][nt][q] = 0.f;

    conv_fill(sbase, tid, 0, y0, o0, b);
    conv_fill(sbase, tid, 1, y0, o0, b);

    for (int it = 0; it < 18; ++it) {
        if (it < 16) CP_WAIT1(); else CP_WAIT0();
        __syncthreads();

        uint32_t stg = sbase + (it & 1) * STAGE_BYTES;
        uint32_t sA = stg + ST_A, sB = stg + ST_B;

#pragma unroll
        for (int ks = 0; ks < 4; ++ks) {
            uint32_t bf[8];
#pragma unroll
            for (int p = 0; p < 2; ++p) {
                int rowB = warpN * 32 + p * 16 + ((lm >> 1) << 3) + r8;
                int unitB = ks * 2 + (lm & 1);
                ldsm4(&bf[p * 4], sw_addr(sB, rowB, unitB));
            }
#pragma unroll
            for (int mt = 0; mt < 4; ++mt) {
                int rowA = warpM * 64 + mt * 16 + ((lm & 1) << 3) + r8;
                int unitA = ks * 2 + (lm >> 1);
                uint32_t af[4];
                ldsm4(af, sw_addr(sA, rowA, unitA));
#pragma unroll
                for (int nt = 0; nt < 4; ++nt)
                    mma_f16(acc[mt][nt], af, &bf[nt * 2]);
            }
        }
        __syncthreads();
        if (it + 2 < 18)
            conv_fill(sbase, tid, it + 2, y0, o0, b);
    }

    // bias triples for both rows into smem
    float* bias_s = (float*)smem;   // [2][128][3]
    if (tid < 256) {
        int r = tid >> 7, o_loc = tid & 127;
        int o = o0 + o_loc;
        int y = y0 + r;
        const float* t = &g_tb[o * 9];
        float f0 = (y >= 1) ? 1.f : 0.f;
        float f2 = (y <= 126) ? 1.f : 0.f;
        bias_s[tid * 3 + 0] = dwb[o] + f0 * t[1] + t[4] + f2 * t[7];
        bias_s[tid * 3 + 1] = f0 * t[0] + t[3] + f2 * t[6];
        bias_s[tid * 3 + 2] = f0 * t[2] + t[5] + f2 * t[8];
    }
    __syncthreads();

    // epilogue: warp covers row r = warpN>>2, x base (warpN&3)*32
    int r = warpN >> 2;
    int y = y0 + r;
    int xb = (warpN & 3) * 32;
    int rr = lane >> 2;
    int q2 = (lane & 3) * 2;
    bool doss = (o0 < 256);
#pragma unroll
    for (int mt = 0; mt < 4; ++mt) {
#pragma unroll
        for (int half = 0; half < 2; ++half) {
            int o_loc = warpM * 64 + mt * 16 + rr + half * 8;
            int o = o0 + o_loc;
            int bi = (r * 128 + o_loc) * 3;
            float base = bias_s[bi + 0];
            float rs0  = bias_s[bi + 1];
            float rs2  = bias_s[bi + 2];
            float ss = 0.f;
            float* dst = g_qkv2 + (size_t)(b * 384 + o) * SPATIAL + y * 128;
#pragma unroll
            for (int nt = 0; nt < 4; ++nt) {
                int x = xb + nt * 8 + q2;
                float v0 = acc[mt][nt][half * 2 + 0] + base + rs2;
                if (x >= 1) v0 += rs0;
                float v1 = acc[mt][nt][half * 2 + 1] + base + rs0;
                if (x + 1 <= 126) v1 += rs2;
                *(float2*)(dst + x) = make_float2(v0, v1);
                ss = fmaf(v0, v0, ss);
                ss = fmaf(v1, v1, ss);
            }
            ss += __shfl_xor_sync(0xffffffffu, ss, 1);
            ss += __shfl_xor_sync(0xffffffffu, ss, 2);
            if (doss && (lane & 3) == 0)
                atomicAdd(&g_ss[b * 256 + o], ss);
        }
    }
}

// ---------------------------------------------------------------------------
// P5: attn partial sums (32 K-slices x 8 bh, atomics).
// ---------------------------------------------------------------------------
__global__ void attn_partial() {
    int slice = blockIdx.x;
    int bh = blockIdx.y;
    int b = bh >> 2, h = bh & 3;
    const float* qb = g_qkv2 + (size_t)(b * 384 + h * 32) * SPATIAL;
    const float* kb = g_qkv2 + (size_t)(b * 384 + 128 + h * 32) * SPATIAL;

    __shared__ float qs[32][65], ks[32][65];
    int tid = threadIdx.x;
    int c = tid >> 3;
    int d0 = (tid & 7) * 4;
    float acc[4] = {0.f, 0.f, 0.f, 0.f};

    for (int sub = 0; sub < 8; ++sub) {
        int s0 = slice * 512 + sub * 64;
        for (int i = tid; i < 2048; i += 256) {
            int cc = i >> 6, kk = i & 63;
            qs[cc][kk] = qb[(size_t)cc * SPATIAL + s0 + kk];
            ks[cc][kk] = kb[(size_t)cc * SPATIAL + s0 + kk];
        }
        __syncthreads();
#pragma unroll 8
        for (int kk = 0; kk < 64; ++kk) {
            float qv = qs[c][kk];
#pragma unroll
            for (int j = 0; j < 4; ++j)
                acc[j] = fmaf(qv, ks[d0 + j][kk], acc[j]);
        }
        __syncthreads();
    }
#pragma unroll
    for (int j = 0; j < 4; ++j)
        atomicAdd(&g_attnP[(bh * 32 + c) * 32 + d0 + j], acc[j]);
}

// ---------------------------------------------------------------------------
// P6: fused norms + softmax + M2 per (b,h).
// M2[b][o][h*32+d] = sum_c Wpo[o][h*32+c] * softmax_row(c)[d]
// ---------------------------------------------------------------------------
__global__ void softmax_M2(const float* __restrict__ temp) {
    int b = blockIdx.x, h = blockIdx.y;
    int bh = b * 4 + h;
    int tid = threadIdx.x, wid = tid >> 5, lane = tid & 31;

    __shared__ float A[32][33];
    __shared__ float W[128][33];

    float tp = temp[h];
    float invk = 1.f / fmaxf(sqrtf(g_ss[b * 256 + 128 + h * 32 + lane]), 1e-12f);
    for (int c = wid; c < 32; c += 8) {
        float invq = 1.f / fmaxf(sqrtf(g_ss[b * 256 + h * 32 + c]), 1e-12f);
        float v = g_attnP[(bh * 32 + c) * 32 + lane] * invq * invk * tp;
        float mx = v;
#pragma unroll
        for (int off = 16; off; off >>= 1)
            mx = fmaxf(mx, __shfl_xor_sync(0xffffffffu, mx, off));
        float e = expf(v - mx);
        float s = e;
#pragma unroll
        for (int off = 16; off; off >>= 1)
            s += __shfl_xor_sync(0xffffffffu, s, off);
        A[c][lane] = e / s;
    }
    for (int i = tid; i < 4096; i += 256) {
        int o = i >> 5, c = i & 31;
        W[o][c] = g_Wpo[o * 128 + h * 32 + c];
    }
    __syncthreads();

    int o = tid >> 1;
    int d0 = (tid & 1) * 16;
#pragma unroll
    for (int dd = 0; dd < 16; ++dd) {
        int d = d0 + dd;
        float s = 0.f;
#pragma unroll
        for (int c = 0; c < 32; ++c)
            s = fmaf(W[o][c], A[c][d], s);
        g_M2[b * 16384 + o * 128 + h * 32 + d] = s;
    }
}

// ---------------------------------------------------------------------------
// P7: out[b][o][s] = sum_dg M2[b][o][dg] * v[b][dg][s] + po_b[o]  (fp32x2)
// ---------------------------------------------------------------------------
__global__ __launch_bounds__(256)
void final_gemm(const float* __restrict__ pob, float* __restrict__ out) {
    int s0 = blockIdx.x * 128;
    int b  = blockIdx.z;
    int tid = threadIdx.x;
    int tr = tid >> 4, tc = tid & 15;

    __shared__ float As[16][128];
    __shared__ float Bs[16][132];

    u64 acc2[4][8];
#pragma unroll
    for (int mp = 0; mp < 4; ++mp)
#pragma unroll
        for (int n = 0; n < 8; ++n) acc2[mp][n] = 0ull;

    for (int cb = 0; cb < 8; ++cb) {
        for (int i = tid; i < 2048; i += 256) {
            int o = i >> 4, kk = i & 15;
            As[kk][o] = g_M2[b * 16384 + o * 128 + cb * 16 + kk];
        }
        for (int i = tid; i < 2048; i += 256) {
            int kk = i >> 7, sx = i & 127;
            Bs[kk][sx] = g_qkv2[(size_t)(b * 384 + 256 + cb * 16 + kk) * SPATIAL + s0 + sx];
        }
        __syncthreads();
#pragma unroll
        for (int kk = 0; kk < 16; ++kk) {
            u64 a2[4];
#pragma unroll
            for (int mp = 0; mp < 4; ++mp)
                a2[mp] = *(const u64*)&As[kk][tr * 8 + 2 * mp];
            const float* brow = &Bs[kk][tc * 8];
            float4 w0 = *(const float4*)brow;
            float4 w1 = *(const float4*)(brow + 4);
            u64 bb[8];
            bb[0] = pack2(w0.x, w0.x); bb[1] = pack2(w0.y, w0.y);
            bb[2] = pack2(w0.z, w0.z); bb[3] = pack2(w0.w, w0.w);
            bb[4] = pack2(w1.x, w1.x); bb[5] = pack2(w1.y, w1.y);
            bb[6] = pack2(w1.z, w1.z); bb[7] = pack2(w1.w, w1.w);
#pragma unroll
            for (int mp = 0; mp < 4; ++mp)
#pragma unroll
                for (int n = 0; n < 8; ++n)
                    acc2[mp][n] = fma2(a2[mp], bb[n], acc2[mp][n]);
        }
        __syncthreads();
    }

#pragma unroll
    for (int mp = 0; mp < 4; ++mp) {
        int oA = tr * 8 + 2 * mp;
        float b0 = pob[oA], b1 = pob[oA + 1];
        float* op0 = out + (size_t)(b * 128 + oA) * SPATIAL + s0 + tc * 8;
        float* op1 = op0 + SPATIAL;
#pragma unroll
        for (int n = 0; n < 8; ++n) {
            float2 v = unpack2(acc2[mp][n]);
            op0[n] = v.x + b0;
            op1[n] = v.y + b1;
        }
    }
}

// ---------------------------------------------------------------------------
extern "C" void kernel_launch(void* const* d_in, const int* in_sizes, int n_in,
                              void* d_out, int out_size) {
    const float* x     = (const float*)d_in[0];
    const float* qkv_r = (const float*)d_in[1];
    const float* qkv_i = (const float*)d_in[2];
    const float* qkv_j = (const float*)d_in[3];
    const float* qkv_k = (const float*)d_in[4];
    const float* qkv_b = (const float*)d_in[5];
    const float* dw_r  = (const float*)d_in[6];
    const float* dw_i  = (const float*)d_in[7];
    const float* dw_j  = (const float*)d_in[8];
    const float* dw_k  = (const float*)d_in[9];
    const float* dw_b  = (const float*)d_in[10];
    const float* po_r  = (const float*)d_in[11];
    const float* po_i  = (const float*)d_in[12];
    const float* po_j  = (const float*)d_in[13];
    const float* po_k  = (const float*)d_in[14];
    const float* po_b  = (const float*)d_in[15];
    const float* temp  = (const float*)d_in[16];
    float* out = (float*)d_out;

    cudaFuncSetAttribute(conv_mma, cudaFuncAttributeMaxDynamicSharedMemorySize,
                         CONV_SMEM);

    // 7 launches; conv is 4th (lands in the profiled slot)
    expand_all<<<(N_QKV + N_DW + N_PO + 255) / 256, 256>>>(
        qkv_r, qkv_i, qkv_j, qkv_k, dw_r, dw_i, dw_j, dw_k,
        po_r, po_i, po_j, po_k);
    weff_o<<<384, 128>>>(qkv_b);
    prep_x<<<dim3(512, 2), 256>>>(x);

    conv_mma<<<dim3(64, 3, 2), 512, CONV_SMEM>>>(dw_b);

    attn_partial<<<dim3(32, 8), 256>>>();
    softmax_M2<<<dim3(2, 4), 256>>>(temp);
    final_gemm<<<dim3(128, 1, 2), 256>>>(po_b, out);
}

// round 11
// speedup vs baseline: 1.1181x; 1.1181x over previous
#include <cuda_runtime.h>
#include <cuda_fp16.h>
#include <cstdint>
#include <math.h>

// ---------------------------------------------------------------------------
// QAttention round 10: round-8 conv geometry (256 thr, 2 CTAs/SM) + hoisted
// ldsm addresses (ALU was 32.5% in-loop), merged tail kernels (7 launches).
// ---------------------------------------------------------------------------

#define SPATIAL 16384
typedef unsigned long long u64;

// ------------------------- mma.sync helpers --------------------------------
__device__ __forceinline__ uint32_t smem_to_u32(const void* p) {
    uint32_t a;
    asm("{ .reg .u64 t; cvta.to.shared.u64 t, %1; cvt.u32.u64 %0, t; }"
        : "=r"(a) : "l"(p));
    return a;
}
__device__ __forceinline__ void ldsm4(uint32_t* r, uint32_t addr) {
    asm volatile("ldmatrix.sync.aligned.m8n8.x4.shared.b16 {%0,%1,%2,%3}, [%4];"
                 : "=r"(r[0]), "=r"(r[1]), "=r"(r[2]), "=r"(r[3]) : "r"(addr));
}
__device__ __forceinline__ void mma_f16(float* d, const uint32_t* a,
                                        const uint32_t* b) {
    asm volatile(
        "mma.sync.aligned.m16n8k16.row.col.f32.f16.f16.f32 "
        "{%0,%1,%2,%3}, {%4,%5,%6,%7}, {%8,%9}, {%0,%1,%2,%3};"
        : "+f"(d[0]), "+f"(d[1]), "+f"(d[2]), "+f"(d[3])
        : "r"(a[0]), "r"(a[1]), "r"(a[2]), "r"(a[3]), "r"(b[0]), "r"(b[1]));
}
__device__ __forceinline__ uint32_t sw_off(int row, int unit) {
    return row * 128 + (((unit) ^ (row & 7)) << 4);
}
__device__ __forceinline__ void cp_async16(uint32_t saddr, const void* gptr,
                                           uint32_t bytes) {
    asm volatile("cp.async.cg.shared.global [%0], [%1], 16, %2;"
                 :: "r"(saddr), "l"(gptr), "r"(bytes) : "memory");
}
#define CP_COMMIT() asm volatile("cp.async.commit_group;" ::: "memory")
#define CP_WAIT1()  asm volatile("cp.async.wait_group 1;" ::: "memory")
#define CP_WAIT0()  asm volatile("cp.async.wait_group 0;" ::: "memory")

// ------------------------- f32x2 helpers (final_gemm) ----------------------
__device__ __forceinline__ u64 pack2(float lo, float hi) {
    u64 r; asm("mov.b64 %0,{%1,%2};" : "=l"(r) : "f"(lo), "f"(hi)); return r;
}
__device__ __forceinline__ float2 unpack2(u64 v) {
    float2 f; asm("mov.b64 {%0,%1},%2;" : "=f"(f.x), "=f"(f.y) : "l"(v)); return f;
}
__device__ __forceinline__ u64 fma2(u64 a, u64 b, u64 c) {
    u64 d; asm("fma.rn.f32x2 %0,%1,%2,%3;" : "=l"(d) : "l"(a), "l"(b), "l"(c)); return d;
}

// ------------------------- device scratch ----------------------------------
__device__ float g_Wqkv[384 * 128];
__device__ float g_Wdw[384 * 384 * 9];
__device__ float g_Wpo[128 * 128];
__device__ __half g_Weff16[384 * 1152];          // [o][tap*128+c]
__device__ float g_tb[384 * 9];
__device__ __half g_xt16[2 * SPATIAL * 128];     // [b][s][c]
__device__ float g_qkv2[2 * 384 * SPATIAL];
__device__ float g_attnP[2 * 4 * 32 * 32];
__device__ float g_ss[2 * 256];
__device__ float g_M2[2 * 128 * 128];

// ---------------------------------------------------------------------------
// P1: all three Hamilton expansions in one kernel.
// ---------------------------------------------------------------------------
__device__ __forceinline__ void ham_one(const float* r, const float* i_,
                                        const float* j_, const float* k_,
                                        float* dst, int idx,
                                        int O4, int C4, int T) {
    int tap = idx % T;
    int rem = idx / T;
    int C = 4 * C4;
    int c = rem % C;
    int o = rem / C;
    int br = o / O4, oo = o % O4;
    int bc = c / C4, cc = c % C4;

    const int   src[16] = {0,1,2,3, 1,0,3,2, 2,3,0,1, 3,2,1,0};
    const float sgn[16] = {1.f,-1.f,-1.f,-1.f, 1.f,1.f,-1.f,1.f,
                           1.f,1.f,1.f,-1.f,  1.f,-1.f,1.f,1.f};
    const float* comp[4] = {r, i_, j_, k_};
    dst[idx] = sgn[br * 4 + bc] * comp[src[br * 4 + bc]][(oo * C4 + cc) * T + tap];
}

#define N_QKV (384 * 128)
#define N_DW  (384 * 384 * 9)
#define N_PO  (128 * 128)

__global__ void expand_all(const float* __restrict__ qr, const float* __restrict__ qi,
                           const float* __restrict__ qj, const float* __restrict__ qk,
                           const float* __restrict__ dr, const float* __restrict__ di,
                           const float* __restrict__ dj, const float* __restrict__ dk,
                           const float* __restrict__ pr, const float* __restrict__ pi,
                           const float* __restrict__ pj, const float* __restrict__ pk) {
    int idx = blockIdx.x * 256 + threadIdx.x;
    if (idx < N_QKV) {
        ham_one(qr, qi, qj, qk, g_Wqkv, idx, 96, 32, 1);
    } else if (idx < N_QKV + N_DW) {
        ham_one(dr, di, dj, dk, g_Wdw, idx - N_QKV, 96, 96, 9);
    } else if (idx < N_QKV + N_DW + N_PO) {
        ham_one(pr, pi, pj, pk, g_Wpo, idx - N_QKV - N_DW, 32, 32, 1);
    }
}

// ---------------------------------------------------------------------------
// P2: Weff per output row -> fp16 at [o][tap*128+c]; tb fold.
// ---------------------------------------------------------------------------
__global__ __launch_bounds__(128)
void weff_o(const float* __restrict__ qkv_b) {
    int o = blockIdx.x;
    int c = threadIdx.x;

    __shared__ float wdw_s[288 + 8];
    __shared__ float wq_s[32 * 128];
    __shared__ float qb_s[384];

    for (int m = c; m < 384; m += 128) qb_s[m] = qkv_b[m];

    float acc[9], tbp[9];
#pragma unroll
    for (int t = 0; t < 9; ++t) { acc[t] = 0.f; tbp[t] = 0.f; }

    const float* wdw_row = g_Wdw + (size_t)o * 3456;

    for (int cb = 0; cb < 12; ++cb) {
        __syncthreads();
        for (int i = c; i < 288; i += 128)
            wdw_s[i] = wdw_row[cb * 288 + i];
        for (int i = c; i < 4096; i += 128) {
            int m = i >> 7, col = i & 127;
            wq_s[m * 128 + col] = g_Wqkv[(cb * 32 + m) * 128 + col];
        }
        __syncthreads();
#pragma unroll 4
        for (int m = 0; m < 32; ++m) {
            float wq = wq_s[m * 128 + c];
#pragma unroll
            for (int t = 0; t < 9; ++t)
                acc[t] = fmaf(wdw_s[m * 9 + t], wq, acc[t]);
        }
        if (c < 32) {
            float qb = qb_s[cb * 32 + c];
#pragma unroll
            for (int t = 0; t < 9; ++t)
                tbp[t] = fmaf(wdw_s[c * 9 + t], qb, tbp[t]);
        }
    }

#pragma unroll
    for (int t = 0; t < 9; ++t)
        g_Weff16[(size_t)o * 1152 + t * 128 + c] = __float2half(acc[t]);

    if (c < 32) {
#pragma unroll
        for (int t = 0; t < 9; ++t) {
            float v = tbp[t];
#pragma unroll
            for (int off = 16; off; off >>= 1)
                v += __shfl_xor_sync(0xffffffffu, v, off);
            if (c == 0) g_tb[o * 9 + t] = v;
        }
    }
}

// ---------------------------------------------------------------------------
// P3: transpose x to [b][s][c] fp16; block(0,0) also zeros scratch.
// ---------------------------------------------------------------------------
__global__ void prep_x(const float* __restrict__ X) {
    __shared__ float t[128][33];
    int s0 = blockIdx.x * 32;
    int b  = blockIdx.y;
    int tid = threadIdx.x;

    if (blockIdx.x == 0 && b == 0) {
        for (int i = tid; i < 8192; i += 256) g_attnP[i] = 0.f;
        for (int i = tid; i < 512; i += 256) g_ss[i] = 0.f;
    }
    for (int i = tid; i < 4096; i += 256) {
        int c = i >> 5, s = i & 31;
        t[c][s] = X[((size_t)(b * 128 + c)) * SPATIAL + s0 + s];
    }
    __syncthreads();
    for (int i = tid; i < 4096; i += 256) {
        int s = i >> 7, c = i & 127;
        g_xt16[((size_t)b * SPATIAL + s0 + s) * 128 + c] = __float2half(t[c][s]);
    }
}

// ---------------------------------------------------------------------------
// P4: conv via mma.sync fp16, round-8 geometry, hoisted ldsm addresses.
// CTA = M128 x N128, 256 threads (8 warps 2Mx4N), warp tile 64x32.
// K: 9 taps x 2 chunks of 64 ch = 18 iterations x 4 k16-steps.
// Stage: A [128][64] 16KB + B [128][64] 16KB = 32KB; x2 = 64KB.
// ---------------------------------------------------------------------------
#define ST_A 0
#define ST_B (16 * 1024)
#define STAGE_BYTES (32 * 1024)
#define CONV_SMEM (2 * STAGE_BYTES)

__device__ __forceinline__ void conv_fill(uint32_t sbase, int tid,
                                          int it, int y, int o0, int b) {
    int tap = it >> 1;
    int ch  = (it & 1) * 64;
    int dy = tap / 3 - 1, dx = tap % 3 - 1;
    uint32_t stg = sbase + (it & 1) * STAGE_BYTES;

    // A: [128 o][64 k] = 1024 x 16B
    for (int i = tid; i < 1024; i += 256) {
        int row = i >> 3, u = i & 7;
        const __half* src = g_Weff16 +
            (size_t)(o0 + row) * 1152 + tap * 128 + ch + u * 8;
        cp_async16(stg + ST_A + sw_off(row, u), src, 16u);
    }
    // B: [128 n][64 k] = 1024 x 16B, (dy,dx)-gathered, zero halo
    int yy = y + dy;
    bool yok = (unsigned)yy < 128u;
    for (int i = tid; i < 1024; i += 256) {
        int n = i >> 3, u = i & 7;
        int xx = n + dx;
        bool ok = yok && ((unsigned)xx < 128u);
        const __half* src = ok
            ? g_xt16 + ((size_t)b * SPATIAL + yy * 128 + xx) * 128 + ch + u * 8
            : g_xt16;
        cp_async16(stg + ST_B + sw_off(n, u), src, ok ? 16u : 0u);
    }
    CP_COMMIT();
}

__global__ __launch_bounds__(256, 2)
void conv_mma(const float* __restrict__ dwb) {
    extern __shared__ char smem[];
    uint32_t sbase = smem_to_u32(smem);
    int tid = threadIdx.x, wid = tid >> 5, lane = tid & 31;
    int y  = blockIdx.x;          // image row
    int o0 = blockIdx.y * 128;    // output-channel tile
    int b  = blockIdx.z;

    int warpM = wid >> 2;         // 0..1 -> 64 chans
    int warpN = wid & 3;          // 0..3 -> 32 pixels
    int lm = lane >> 3;
    int r8 = lane & 7;

    // hoisted fragment offsets (relative to stage base)
    uint32_t offA[4][4];          // [mt][ks]
    uint32_t offB[4][2];          // [ks][p]
#pragma unroll
    for (int ks = 0; ks < 4; ++ks) {
#pragma unroll
        for (int mt = 0; mt < 4; ++mt) {
            int rowA = warpM * 64 + mt * 16 + ((lm & 1) << 3) + r8;
            offA[mt][ks] = ST_A + sw_off(rowA, ks * 2 + (lm >> 1));
        }
#pragma unroll
        for (int p = 0; p < 2; ++p) {
            int rowB = warpN * 32 + p * 16 + ((lm >> 1) << 3) + r8;
            offB[ks][p] = ST_B + sw_off(rowB, ks * 2 + (lm & 1));
        }
    }

    float acc[4][4][4];
#pragma unroll
    for (int mt = 0; mt < 4; ++mt)
#pragma unroll
        for (int nt = 0; nt < 4; ++nt)
#pragma unroll
            for (int q = 0; q < 4; ++q) acc[mt][nt][q] = 0.f;

    conv_fill(sbase, tid, 0, y, o0, b);
    conv_fill(sbase, tid, 1, y, o0, b);

    for (int it = 0; it < 18; ++it) {
        if (it < 16) CP_WAIT1(); else CP_WAIT0();
        __syncthreads();

        uint32_t stg = sbase + (it & 1) * STAGE_BYTES;

#pragma unroll
        for (int ks = 0; ks < 4; ++ks) {
            uint32_t bf[8];
            ldsm4(&bf[0], stg + offB[ks][0]);
            ldsm4(&bf[4], stg + offB[ks][1]);
#pragma unroll
            for (int mt = 0; mt < 4; ++mt) {
                uint32_t af[4];
                ldsm4(af, stg + offA[mt][ks]);
#pragma unroll
                for (int nt = 0; nt < 4; ++nt)
                    mma_f16(acc[mt][nt], af, &bf[nt * 2]);
            }
        }
        __syncthreads();
        if (it + 2 < 18)
            conv_fill(sbase, tid, it + 2, y, o0, b);
    }

    // bias triple per local o into smem
    float* bias_s = (float*)smem;   // [128][3]
    if (tid < 128) {
        int o = o0 + tid;
        const float* t = &g_tb[o * 9];
        float f0 = (y >= 1) ? 1.f : 0.f;
        float f2 = (y <= 126) ? 1.f : 0.f;
        bias_s[tid * 3 + 0] = dwb[o] + f0 * t[1] + t[4] + f2 * t[7];
        bias_s[tid * 3 + 1] = f0 * t[0] + t[3] + f2 * t[6];
        bias_s[tid * 3 + 2] = f0 * t[2] + t[5] + f2 * t[8];
    }
    __syncthreads();

    int rr = lane >> 2;
    int q2 = (lane & 3) * 2;
    bool doss = (o0 < 256);
#pragma unroll
    for (int mt = 0; mt < 4; ++mt) {
#pragma unroll
        for (int half = 0; half < 2; ++half) {
            int o_loc = warpM * 64 + mt * 16 + rr + half * 8;
            int o = o0 + o_loc;
            float base = bias_s[o_loc * 3 + 0];
            float rs0  = bias_s[o_loc * 3 + 1];
            float rs2  = bias_s[o_loc * 3 + 2];
            float ss = 0.f;
            float* dst = g_qkv2 + (size_t)(b * 384 + o) * SPATIAL + y * 128;
#pragma unroll
            for (int nt = 0; nt < 4; ++nt) {
                int x = warpN * 32 + nt * 8 + q2;
                float v0 = acc[mt][nt][half * 2 + 0] + base + rs2;
                if (x >= 1) v0 += rs0;
                float v1 = acc[mt][nt][half * 2 + 1] + base + rs0;
                if (x + 1 <= 126) v1 += rs2;
                *(float2*)(dst + x) = make_float2(v0, v1);
                ss = fmaf(v0, v0, ss);
                ss = fmaf(v1, v1, ss);
            }
            ss += __shfl_xor_sync(0xffffffffu, ss, 1);
            ss += __shfl_xor_sync(0xffffffffu, ss, 2);
            if (doss && (lane & 3) == 0)
                atomicAdd(&g_ss[b * 256 + o], ss);
        }
    }
}

// ---------------------------------------------------------------------------
// P5: attn partial sums (32 K-slices x 8 bh, atomics).
// ---------------------------------------------------------------------------
__global__ void attn_partial() {
    int slice = blockIdx.x;
    int bh = blockIdx.y;
    int b = bh >> 2, h = bh & 3;
    const float* qb = g_qkv2 + (size_t)(b * 384 + h * 32) * SPATIAL;
    const float* kb = g_qkv2 + (size_t)(b * 384 + 128 + h * 32) * SPATIAL;

    __shared__ float qs[32][65], ks[32][65];
    int tid = threadIdx.x;
    int c = tid >> 3;
    int d0 = (tid & 7) * 4;
    float acc[4] = {0.f, 0.f, 0.f, 0.f};

    for (int sub = 0; sub < 8; ++sub) {
        int s0 = slice * 512 + sub * 64;
        for (int i = tid; i < 2048; i += 256) {
            int cc = i >> 6, kk = i & 63;
            qs[cc][kk] = qb[(size_t)cc * SPATIAL + s0 + kk];
            ks[cc][kk] = kb[(size_t)cc * SPATIAL + s0 + kk];
        }
        __syncthreads();
#pragma unroll 8
        for (int kk = 0; kk < 64; ++kk) {
            float qv = qs[c][kk];
#pragma unroll
            for (int j = 0; j < 4; ++j)
                acc[j] = fmaf(qv, ks[d0 + j][kk], acc[j]);
        }
        __syncthreads();
    }
#pragma unroll
    for (int j = 0; j < 4; ++j)
        atomicAdd(&g_attnP[(bh * 32 + c) * 32 + d0 + j], acc[j]);
}

// ---------------------------------------------------------------------------
// P6: fused norms + softmax + M2 per (b,h).
// ---------------------------------------------------------------------------
__global__ void softmax_M2(const float* __restrict__ temp) {
    int b = blockIdx.x, h = blockIdx.y;
    int bh = b * 4 + h;
    int tid = threadIdx.x, wid = tid >> 5, lane = tid & 31;

    __shared__ float A[32][33];
    __shared__ float W[128][33];

    float tp = temp[h];
    float invk = 1.f / fmaxf(sqrtf(g_ss[b * 256 + 128 + h * 32 + lane]), 1e-12f);
    for (int c = wid; c < 32; c += 8) {
        float invq = 1.f / fmaxf(sqrtf(g_ss[b * 256 + h * 32 + c]), 1e-12f);
        float v = g_attnP[(bh * 32 + c) * 32 + lane] * invq * invk * tp;
        float mx = v;
#pragma unroll
        for (int off = 16; off; off >>= 1)
            mx = fmaxf(mx, __shfl_xor_sync(0xffffffffu, mx, off));
        float e = expf(v - mx);
        float s = e;
#pragma unroll
        for (int off = 16; off; off >>= 1)
            s += __shfl_xor_sync(0xffffffffu, s, off);
        A[c][lane] = e / s;
    }
    for (int i = tid; i < 4096; i += 256) {
        int o = i >> 5, c = i & 31;
        W[o][c] = g_Wpo[o * 128 + h * 32 + c];
    }
    __syncthreads();

    int o = tid >> 1;
    int d0 = (tid & 1) * 16;
#pragma unroll
    for (int dd = 0; dd < 16; ++dd) {
        int d = d0 + dd;
        float s = 0.f;
#pragma unroll
        for (int c = 0; c < 32; ++c)
            s = fmaf(W[o][c], A[c][d], s);
        g_M2[b * 16384 + o * 128 + h * 32 + d] = s;
    }
}

// ---------------------------------------------------------------------------
// P7: out[b][o][s] = sum_dg M2[b][o][dg] * v[b][dg][s] + po_b[o]  (fp32x2)
// ---------------------------------------------------------------------------
__global__ __launch_bounds__(256)
void final_gemm(const float* __restrict__ pob, float* __restrict__ out) {
    int s0 = blockIdx.x * 128;
    int b  = blockIdx.z;
    int tid = threadIdx.x;
    int tr = tid >> 4, tc = tid & 15;

    __shared__ float As[16][128];
    __shared__ float Bs[16][132];

    u64 acc2[4][8];
#pragma unroll
    for (int mp = 0; mp < 4; ++mp)
#pragma unroll
        for (int n = 0; n < 8; ++n) acc2[mp][n] = 0ull;

    for (int cb = 0; cb < 8; ++cb) {
        for (int i = tid; i < 2048; i += 256) {
            int o = i >> 4, kk = i & 15;
            As[kk][o] = g_M2[b * 16384 + o * 128 + cb * 16 + kk];
        }
        for (int i = tid; i < 2048; i += 256) {
            int kk = i >> 7, sx = i & 127;
            Bs[kk][sx] = g_qkv2[(size_t)(b * 384 + 256 + cb * 16 + kk) * SPATIAL + s0 + sx];
        }
        __syncthreads();
#pragma unroll
        for (int kk = 0; kk < 16; ++kk) {
            u64 a2[4];
#pragma unroll
            for (int mp = 0; mp < 4; ++mp)
                a2[mp] = *(const u64*)&As[kk][tr * 8 + 2 * mp];
            const float* brow = &Bs[kk][tc * 8];
            float4 w0 = *(const float4*)brow;
            float4 w1 = *(const float4*)(brow + 4);
            u64 bb[8];
            bb[0] = pack2(w0.x, w0.x); bb[1] = pack2(w0.y, w0.y);
            bb[2] = pack2(w0.z, w0.z); bb[3] = pack2(w0.w, w0.w);
            bb[4] = pack2(w1.x, w1.x); bb[5] = pack2(w1.y, w1.y);
            bb[6] = pack2(w1.z, w1.z); bb[7] = pack2(w1.w, w1.w);
#pragma unroll
            for (int mp = 0; mp < 4; ++mp)
#pragma unroll
                for (int n = 0; n < 8; ++n)
                    acc2[mp][n] = fma2(a2[mp], bb[n], acc2[mp][n]);
        }
        __syncthreads();
    }

#pragma unroll
    for (int mp = 0; mp < 4; ++mp) {
        int oA = tr * 8 + 2 * mp;
        float b0 = pob[oA], b1 = pob[oA + 1];
        float* op0 = out + (size_t)(b * 128 + oA) * SPATIAL + s0 + tc * 8;
        float* op1 = op0 + SPATIAL;
#pragma unroll
        for (int n = 0; n < 8; ++n) {
            float2 v = unpack2(acc2[mp][n]);
            op0[n] = v.x + b0;
            op1[n] = v.y + b1;
        }
    }
}

// ---------------------------------------------------------------------------
extern "C" void kernel_launch(void* const* d_in, const int* in_sizes, int n_in,
                              void* d_out, int out_size) {
    const float* x     = (const float*)d_in[0];
    const float* qkv_r = (const float*)d_in[1];
    const float* qkv_i = (const float*)d_in[2];
    const float* qkv_j = (const float*)d_in[3];
    const float* qkv_k = (const float*)d_in[4];
    const float* qkv_b = (const float*)d_in[5];
    const float* dw_r  = (const float*)d_in[6];
    const float* dw_i  = (const float*)d_in[7];
    const float* dw_j  = (const float*)d_in[8];
    const float* dw_k  = (const float*)d_in[9];
    const float* dw_b  = (const float*)d_in[10];
    const float* po_r  = (const float*)d_in[11];
    const float* po_i  = (const float*)d_in[12];
    const float* po_j  = (const float*)d_in[13];
    const float* po_k  = (const float*)d_in[14];
    const float* po_b  = (const float*)d_in[15];
    const float* temp  = (const float*)d_in[16];
    float* out = (float*)d_out;

    cudaFuncSetAttribute(conv_mma, cudaFuncAttributeMaxDynamicSharedMemorySize,
                         CONV_SMEM);

    // 7 launches; conv is 4th (profiled slot)
    expand_all<<<(N_QKV + N_DW + N_PO + 255) / 256, 256>>>(
        qkv_r, qkv_i, qkv_j, qkv_k, dw_r, dw_i, dw_j, dw_k,
        po_r, po_i, po_j, po_k);
    weff_o<<<384, 128>>>(qkv_b);
    prep_x<<<dim3(512, 2), 256>>>(x);

    conv_mma<<<dim3(128, 3, 2), 256, CONV_SMEM>>>(dw_b);

    attn_partial<<<dim3(32, 8), 256>>>();
    softmax_M2<<<dim3(2, 4), 256>>>(temp);
    final_gemm<<<dim3(128, 1, 2), 256>>>(po_b, out);
}

// round 12
// speedup vs baseline: 1.3809x; 1.2351x over previous
#include <cuda_runtime.h>
#include <cuda_fp16.h>
#include <cstdint>
#include <math.h>

// ---------------------------------------------------------------------------
// QAttention round 11:
//  - conv: fill-ALU eliminated (invariant base ptrs + validity mask),
//    3-stage cp.async ring (96KB, 2 CTAs/SM), one barrier/iteration.
//  - final projection on fp16 HMMA (M2 fp16 + v fp16 via prep_v transpose).
//  - attn_partial with transposed k tile + float4 smem reads.
// ---------------------------------------------------------------------------

#define SPATIAL 16384
typedef unsigned long long u64;

// ------------------------- mma.sync helpers --------------------------------
__device__ __forceinline__ uint32_t smem_to_u32(const void* p) {
    uint32_t a;
    asm("{ .reg .u64 t; cvta.to.shared.u64 t, %1; cvt.u32.u64 %0, t; }"
        : "=r"(a) : "l"(p));
    return a;
}
__device__ __forceinline__ void ldsm4(uint32_t* r, uint32_t addr) {
    asm volatile("ldmatrix.sync.aligned.m8n8.x4.shared.b16 {%0,%1,%2,%3}, [%4];"
                 : "=r"(r[0]), "=r"(r[1]), "=r"(r[2]), "=r"(r[3]) : "r"(addr));
}
__device__ __forceinline__ void mma_f16(float* d, const uint32_t* a,
                                        const uint32_t* b) {
    asm volatile(
        "mma.sync.aligned.m16n8k16.row.col.f32.f16.f16.f32 "
        "{%0,%1,%2,%3}, {%4,%5,%6,%7}, {%8,%9}, {%0,%1,%2,%3};"
        : "+f"(d[0]), "+f"(d[1]), "+f"(d[2]), "+f"(d[3])
        : "r"(a[0]), "r"(a[1]), "r"(a[2]), "r"(a[3]), "r"(b[0]), "r"(b[1]));
}
__device__ __forceinline__ uint32_t sw_off(int row, int unit) {
    return row * 128 + (((unit) ^ (row & 7)) << 4);
}
__device__ __forceinline__ void cp_async16(uint32_t saddr, const void* gptr,
                                           uint32_t bytes) {
    asm volatile("cp.async.cg.shared.global [%0], [%1], 16, %2;"
                 :: "r"(saddr), "l"(gptr), "r"(bytes) : "memory");
}
#define CP_COMMIT() asm volatile("cp.async.commit_group;" ::: "memory")
#define CP_WAIT1()  asm volatile("cp.async.wait_group 1;" ::: "memory")
#define CP_WAIT0()  asm volatile("cp.async.wait_group 0;" ::: "memory")

// ------------------------- device scratch ----------------------------------
__device__ float g_Wqkv[384 * 128];
__device__ float g_Wdw[384 * 384 * 9];
__device__ float g_Wpo[128 * 128];
__device__ __half g_Weff16[384 * 1152];          // [o][tap*128+c]
__device__ float g_tb[384 * 9];
__device__ __half g_xt16[2 * SPATIAL * 128];     // [b][s][c]
__device__ float g_qkv2[2 * 384 * SPATIAL];
__device__ __half g_v16[2 * SPATIAL * 128];      // [b][s][d] (v channels)
__device__ float g_attnP[2 * 4 * 32 * 32];
__device__ float g_ss[2 * 256];
__device__ __half g_M2h[2 * 128 * 128];          // fp16 po@attn

// ---------------------------------------------------------------------------
// P1: all three Hamilton expansions in one kernel.
// ---------------------------------------------------------------------------
__device__ __forceinline__ void ham_one(const float* r, const float* i_,
                                        const float* j_, const float* k_,
                                        float* dst, int idx,
                                        int O4, int C4, int T) {
    int tap = idx % T;
    int rem = idx / T;
    int C = 4 * C4;
    int c = rem % C;
    int o = rem / C;
    int br = o / O4, oo = o % O4;
    int bc = c / C4, cc = c % C4;

    const int   src[16] = {0,1,2,3, 1,0,3,2, 2,3,0,1, 3,2,1,0};
    const float sgn[16] = {1.f,-1.f,-1.f,-1.f, 1.f,1.f,-1.f,1.f,
                           1.f,1.f,1.f,-1.f,  1.f,-1.f,1.f,1.f};
    const float* comp[4] = {r, i_, j_, k_};
    dst[idx] = sgn[br * 4 + bc] * comp[src[br * 4 + bc]][(oo * C4 + cc) * T + tap];
}

#define N_QKV (384 * 128)
#define N_DW  (384 * 384 * 9)
#define N_PO  (128 * 128)

__global__ void expand_all(const float* __restrict__ qr, const float* __restrict__ qi,
                           const float* __restrict__ qj, const float* __restrict__ qk,
                           const float* __restrict__ dr, const float* __restrict__ di,
                           const float* __restrict__ dj, const float* __restrict__ dk,
                           const float* __restrict__ pr, const float* __restrict__ pi,
                           const float* __restrict__ pj, const float* __restrict__ pk) {
    int idx = blockIdx.x * 256 + threadIdx.x;
    if (idx < N_QKV) {
        ham_one(qr, qi, qj, qk, g_Wqkv, idx, 96, 32, 1);
    } else if (idx < N_QKV + N_DW) {
        ham_one(dr, di, dj, dk, g_Wdw, idx - N_QKV, 96, 96, 9);
    } else if (idx < N_QKV + N_DW + N_PO) {
        ham_one(pr, pi, pj, pk, g_Wpo, idx - N_QKV - N_DW, 32, 32, 1);
    }
}

// ---------------------------------------------------------------------------
// P2: Weff per output row -> fp16 at [o][tap*128+c]; tb fold.
// ---------------------------------------------------------------------------
__global__ __launch_bounds__(128)
void weff_o(const float* __restrict__ qkv_b) {
    int o = blockIdx.x;
    int c = threadIdx.x;

    __shared__ float wdw_s[288 + 8];
    __shared__ float wq_s[32 * 128];
    __shared__ float qb_s[384];

    for (int m = c; m < 384; m += 128) qb_s[m] = qkv_b[m];

    float acc[9], tbp[9];
#pragma unroll
    for (int t = 0; t < 9; ++t) { acc[t] = 0.f; tbp[t] = 0.f; }

    const float* wdw_row = g_Wdw + (size_t)o * 3456;

    for (int cb = 0; cb < 12; ++cb) {
        __syncthreads();
        for (int i = c; i < 288; i += 128)
            wdw_s[i] = wdw_row[cb * 288 + i];
        for (int i = c; i < 4096; i += 128) {
            int m = i >> 7, col = i & 127;
            wq_s[m * 128 + col] = g_Wqkv[(cb * 32 + m) * 128 + col];
        }
        __syncthreads();
#pragma unroll 4
        for (int m = 0; m < 32; ++m) {
            float wq = wq_s[m * 128 + c];
#pragma unroll
            for (int t = 0; t < 9; ++t)
                acc[t] = fmaf(wdw_s[m * 9 + t], wq, acc[t]);
        }
        if (c < 32) {
            float qb = qb_s[cb * 32 + c];
#pragma unroll
            for (int t = 0; t < 9; ++t)
                tbp[t] = fmaf(wdw_s[c * 9 + t], qb, tbp[t]);
        }
    }

#pragma unroll
    for (int t = 0; t < 9; ++t)
        g_Weff16[(size_t)o * 1152 + t * 128 + c] = __float2half(acc[t]);

    if (c < 32) {
#pragma unroll
        for (int t = 0; t < 9; ++t) {
            float v = tbp[t];
#pragma unroll
            for (int off = 16; off; off >>= 1)
                v += __shfl_xor_sync(0xffffffffu, v, off);
            if (c == 0) g_tb[o * 9 + t] = v;
        }
    }
}

// ---------------------------------------------------------------------------
// P3: transpose x to [b][s][c] fp16; block(0,0) also zeros scratch.
// ---------------------------------------------------------------------------
__global__ void prep_x(const float* __restrict__ X) {
    __shared__ float t[128][33];
    int s0 = blockIdx.x * 32;
    int b  = blockIdx.y;
    int tid = threadIdx.x;

    if (blockIdx.x == 0 && b == 0) {
        for (int i = tid; i < 8192; i += 256) g_attnP[i] = 0.f;
        for (int i = tid; i < 512; i += 256) g_ss[i] = 0.f;
    }
    for (int i = tid; i < 4096; i += 256) {
        int c = i >> 5, s = i & 31;
        t[c][s] = X[((size_t)(b * 128 + c)) * SPATIAL + s0 + s];
    }
    __syncthreads();
    for (int i = tid; i < 4096; i += 256) {
        int s = i >> 7, c = i & 127;
        g_xt16[((size_t)b * SPATIAL + s0 + s) * 128 + c] = __float2half(t[c][s]);
    }
}

// ---------------------------------------------------------------------------
// P4: conv via mma.sync fp16, 3-stage cp.async ring, invariant fill addresses.
// CTA = M128 x N128, 256 threads (8 warps 2Mx4N), warp tile 64x32.
// K: 9 taps x 2 chunks of 64 ch = 18 iterations x 4 k16-steps.
// Stage: A 16KB + B 16KB = 32KB; 3 stages = 96KB (2 CTAs/SM).
// ---------------------------------------------------------------------------
#define ST_A 0
#define ST_B (16 * 1024)
#define STAGE_BYTES (32 * 1024)
#define CONV_SMEM (3 * STAGE_BYTES)

__global__ __launch_bounds__(256, 2)
void conv_mma(const float* __restrict__ dwb) {
    extern __shared__ char smem[];
    uint32_t sbase = smem_to_u32(smem);
    int tid = threadIdx.x, wid = tid >> 5, lane = tid & 31;
    int y  = blockIdx.x;          // image row
    int o0 = blockIdx.y * 128;    // output-channel tile
    int b  = blockIdx.z;

    int warpM = wid >> 2;         // 0..1 -> 64 chans
    int warpN = wid & 3;          // 0..3 -> 32 pixels
    int lm = lane >> 3;
    int r8 = lane & 7;

    // ---- invariant fill state (row jumps of 32 fold to +j*const) ----
    int rowT = tid >> 3, uT = tid & 7;
    const __half* pA0 = g_Weff16 + (size_t)(o0 + rowT) * 1152 + uT * 8;
    const __half* pB0 = g_xt16 + ((size_t)b * SPATIAL + y * 128 + rowT) * 128 + uT * 8;
    uint32_t dA0 = ST_A + sw_off(rowT, uT);
    uint32_t dB0 = ST_B + sw_off(rowT, uT);
    uint32_t maskB[4];
#pragma unroll
    for (int j = 0; j < 4; ++j) {
        int n = rowT + 32 * j;
        uint32_t m = 0;
        for (int it = 0; it < 18; ++it) {
            int tap = it >> 1;
            int dy = tap / 3 - 1, dx = tap % 3 - 1;
            bool ok = ((unsigned)(y + dy) < 128u) && ((unsigned)(n + dx) < 128u);
            m |= (ok ? 1u : 0u) << it;
        }
        maskB[j] = m;
    }

    // hoisted ldsm fragment offsets (stage-relative)
    uint32_t offA[4][4], offB[4][2];
#pragma unroll
    for (int ks = 0; ks < 4; ++ks) {
#pragma unroll
        for (int mt = 0; mt < 4; ++mt) {
            int rowA = warpM * 64 + mt * 16 + ((lm & 1) << 3) + r8;
            offA[mt][ks] = ST_A + sw_off(rowA, ks * 2 + (lm >> 1));
        }
#pragma unroll
        for (int p = 0; p < 2; ++p) {
            int rowB = warpN * 32 + p * 16 + ((lm >> 1) << 3) + r8;
            offB[ks][p] = ST_B + sw_off(rowB, ks * 2 + (lm & 1));
        }
    }

    float acc[4][4][4];
#pragma unroll
    for (int mt = 0; mt < 4; ++mt)
#pragma unroll
        for (int nt = 0; nt < 4; ++nt)
#pragma unroll
            for (int q = 0; q < 4; ++q) acc[mt][nt][q] = 0.f;

    auto do_fill = [&](uint32_t stg, int it2) {
        int tap = it2 >> 1;
        int dy = tap / 3 - 1, dx = tap - (tap / 3) * 3 - 1;
        int goff = (dy * 128 + dx) * 128 + ((it2 & 1) << 6);
#pragma unroll
        for (int j = 0; j < 4; ++j)
            cp_async16(stg + dA0 + j * 4096, pA0 + it2 * 64 + j * 36864, 16u);
#pragma unroll
        for (int j = 0; j < 4; ++j) {
            uint32_t ok = (maskB[j] >> it2) & 1u;
            const __half* s = ok ? (pB0 + goff + j * 4096) : g_xt16;
            cp_async16(stg + dB0 + j * 4096, s, ok ? 16u : 0u);
        }
        CP_COMMIT();
    };

    do_fill(sbase, 0);
    do_fill(sbase + STAGE_BYTES, 1);

    uint32_t cs = 0, fs = 2 * STAGE_BYTES;
    for (int it = 0; it < 18; ++it) {
        if (it < 16) CP_WAIT1(); else CP_WAIT0();
        __syncthreads();
        if (it + 2 < 18) do_fill(sbase + fs, it + 2);

        uint32_t stg = sbase + cs;
#pragma unroll
        for (int ks = 0; ks < 4; ++ks) {
            uint32_t bf[8];
            ldsm4(&bf[0], stg + offB[ks][0]);
            ldsm4(&bf[4], stg + offB[ks][1]);
#pragma unroll
            for (int mt = 0; mt < 4; ++mt) {
                uint32_t af[4];
                ldsm4(af, stg + offA[mt][ks]);
#pragma unroll
                for (int nt = 0; nt < 4; ++nt)
                    mma_f16(acc[mt][nt], af, &bf[nt * 2]);
            }
        }
        cs += STAGE_BYTES; if (cs == 3 * STAGE_BYTES) cs = 0;
        fs += STAGE_BYTES; if (fs == 3 * STAGE_BYTES) fs = 0;
    }
    __syncthreads();

    // bias triple per local o into smem
    float* bias_s = (float*)smem;   // [128][3]
    if (tid < 128) {
        int o = o0 + tid;
        const float* t = &g_tb[o * 9];
        float f0 = (y >= 1) ? 1.f : 0.f;
        float f2 = (y <= 126) ? 1.f : 0.f;
        bias_s[tid * 3 + 0] = dwb[o] + f0 * t[1] + t[4] + f2 * t[7];
        bias_s[tid * 3 + 1] = f0 * t[0] + t[3] + f2 * t[6];
        bias_s[tid * 3 + 2] = f0 * t[2] + t[5] + f2 * t[8];
    }
    __syncthreads();

    int rr = lane >> 2;
    int q2 = (lane & 3) * 2;
    bool doss = (o0 < 256);
#pragma unroll
    for (int mt = 0; mt < 4; ++mt) {
#pragma unroll
        for (int half = 0; half < 2; ++half) {
            int o_loc = warpM * 64 + mt * 16 + rr + half * 8;
            int o = o0 + o_loc;
            float base = bias_s[o_loc * 3 + 0];
            float rs0  = bias_s[o_loc * 3 + 1];
            float rs2  = bias_s[o_loc * 3 + 2];
            float ss = 0.f;
            float* dst = g_qkv2 + (size_t)(b * 384 + o) * SPATIAL + y * 128;
#pragma unroll
            for (int nt = 0; nt < 4; ++nt) {
                int x = warpN * 32 + nt * 8 + q2;
                float v0 = acc[mt][nt][half * 2 + 0] + base + rs2;
                if (x >= 1) v0 += rs0;
                float v1 = acc[mt][nt][half * 2 + 1] + base + rs0;
                if (x + 1 <= 126) v1 += rs2;
                *(float2*)(dst + x) = make_float2(v0, v1);
                ss = fmaf(v0, v0, ss);
                ss = fmaf(v1, v1, ss);
            }
            ss += __shfl_xor_sync(0xffffffffu, ss, 1);
            ss += __shfl_xor_sync(0xffffffffu, ss, 2);
            if (doss && (lane & 3) == 0)
                atomicAdd(&g_ss[b * 256 + o], ss);
        }
    }
}

// ---------------------------------------------------------------------------
// P5: transpose v channels of qkv2 -> g_v16 [b][s][d] fp16.
// ---------------------------------------------------------------------------
__global__ void prep_v() {
    __shared__ float t[128][33];
    int s0 = blockIdx.x * 32;
    int b  = blockIdx.y;
    int tid = threadIdx.x;

    for (int i = tid; i < 4096; i += 256) {
        int c = i >> 5, s = i & 31;
        t[c][s] = g_qkv2[(size_t)(b * 384 + 256 + c) * SPATIAL + s0 + s];
    }
    __syncthreads();
    for (int i = tid; i < 4096; i += 256) {
        int s = i >> 7, c = i & 127;
        g_v16[((size_t)b * SPATIAL + s0 + s) * 128 + c] = __float2half(t[c][s]);
    }
}

// ---------------------------------------------------------------------------
// P6: attn partial sums; k tile transposed in smem, float4 reads.
// ---------------------------------------------------------------------------
__global__ void attn_partial() {
    int slice = blockIdx.x;
    int bh = blockIdx.y;
    int b = bh >> 2, h = bh & 3;
    const float* qb = g_qkv2 + (size_t)(b * 384 + h * 32) * SPATIAL;
    const float* kb = g_qkv2 + (size_t)(b * 384 + 128 + h * 32) * SPATIAL;

    __shared__ float qs[32][68];     // [c][kk], row 272B (16B aligned)
    __shared__ float kt[64][36];     // [kk][d], row 144B (16B aligned)
    int tid = threadIdx.x;
    int c = tid >> 3;
    int d0 = (tid & 7) * 4;
    float acc[4] = {0.f, 0.f, 0.f, 0.f};

    for (int sub = 0; sub < 8; ++sub) {
        int s0 = slice * 512 + sub * 64;
        for (int i = tid; i < 2048; i += 256) {
            int cc = i >> 6, kk = i & 63;
            qs[cc][kk] = qb[(size_t)cc * SPATIAL + s0 + kk];
            kt[kk][cc] = kb[(size_t)cc * SPATIAL + s0 + kk];
        }
        __syncthreads();
#pragma unroll 4
        for (int kk = 0; kk < 64; kk += 4) {
            float4 q = *(const float4*)&qs[c][kk];
#pragma unroll
            for (int e = 0; e < 4; ++e) {
                float qe = (&q.x)[e];
                float4 kv = *(const float4*)&kt[kk + e][d0];
                acc[0] = fmaf(qe, kv.x, acc[0]);
                acc[1] = fmaf(qe, kv.y, acc[1]);
                acc[2] = fmaf(qe, kv.z, acc[2]);
                acc[3] = fmaf(qe, kv.w, acc[3]);
            }
        }
        __syncthreads();
    }
#pragma unroll
    for (int j = 0; j < 4; ++j)
        atomicAdd(&g_attnP[(bh * 32 + c) * 32 + d0 + j], acc[j]);
}

// ---------------------------------------------------------------------------
// P7: fused norms + softmax + M2 per (b,h); M2 emitted in fp16.
// ---------------------------------------------------------------------------
__global__ void softmax_M2(const float* __restrict__ temp) {
    int b = blockIdx.x, h = blockIdx.y;
    int bh = b * 4 + h;
    int tid = threadIdx.x, wid = tid >> 5, lane = tid & 31;

    __shared__ float A[32][33];
    __shared__ float W[128][33];

    float tp = temp[h];
    float invk = 1.f / fmaxf(sqrtf(g_ss[b * 256 + 128 + h * 32 + lane]), 1e-12f);
    for (int c = wid; c < 32; c += 8) {
        float invq = 1.f / fmaxf(sqrtf(g_ss[b * 256 + h * 32 + c]), 1e-12f);
        float v = g_attnP[(bh * 32 + c) * 32 + lane] * invq * invk * tp;
        float mx = v;
#pragma unroll
        for (int off = 16; off; off >>= 1)
            mx = fmaxf(mx, __shfl_xor_sync(0xffffffffu, mx, off));
        float e = expf(v - mx);
        float s = e;
#pragma unroll
        for (int off = 16; off; off >>= 1)
            s += __shfl_xor_sync(0xffffffffu, s, off);
        A[c][lane] = e / s;
    }
    for (int i = tid; i < 4096; i += 256) {
        int o = i >> 5, c = i & 31;
        W[o][c] = g_Wpo[o * 128 + h * 32 + c];
    }
    __syncthreads();

    int o = tid >> 1;
    int d0 = (tid & 1) * 16;
#pragma unroll
    for (int dd = 0; dd < 16; ++dd) {
        int d = d0 + dd;
        float s = 0.f;
#pragma unroll
        for (int c = 0; c < 32; ++c)
            s = fmaf(W[o][c], A[c][d], s);
        g_M2h[b * 16384 + o * 128 + h * 32 + d] = __float2half(s);
    }
}

// ---------------------------------------------------------------------------
// P8: out = M2h @ v16 + po_b  via fp16 HMMA. CTA = M128 x N128, K=128.
// smem: A [2kc][128][64] 32KB + B [2kc][128][64] 32KB = 64KB, single shot.
// ---------------------------------------------------------------------------
#define FG_A 0
#define FG_B (32 * 1024)
#define FG_SMEM (64 * 1024)

__global__ __launch_bounds__(256)
void final_mma(const float* __restrict__ pob, float* __restrict__ out) {
    extern __shared__ char smem[];
    uint32_t sbase = smem_to_u32(smem);
    int tid = threadIdx.x, wid = tid >> 5, lane = tid & 31;
    int s0 = blockIdx.x * 128;
    int b  = blockIdx.z;

    int warpM = wid >> 2;
    int warpN = wid & 3;
    int lm = lane >> 3;
    int r8 = lane & 7;

    // fill A (M2h) and B (v16): 2048 x 16B each
    for (int i = tid; i < 2048; i += 256) {
        int kc = i >> 10, row = (i >> 3) & 127, u = i & 7;
        const __half* sa = g_M2h + (size_t)b * 16384 + row * 128 + kc * 64 + u * 8;
        cp_async16(sbase + FG_A + kc * 16384 + sw_off(row, u), sa, 16u);
        const __half* sb = g_v16 + ((size_t)b * SPATIAL + s0 + row) * 128 + kc * 64 + u * 8;
        cp_async16(sbase + FG_B + kc * 16384 + sw_off(row, u), sb, 16u);
    }
    CP_COMMIT();
    CP_WAIT0();
    __syncthreads();

    float acc[4][4][4];
#pragma unroll
    for (int mt = 0; mt < 4; ++mt)
#pragma unroll
        for (int nt = 0; nt < 4; ++nt)
#pragma unroll
            for (int q = 0; q < 4; ++q) acc[mt][nt][q] = 0.f;

#pragma unroll
    for (int kc = 0; kc < 2; ++kc) {
        uint32_t stgA = sbase + FG_A + kc * 16384;
        uint32_t stgB = sbase + FG_B + kc * 16384;
#pragma unroll
        for (int ks = 0; ks < 4; ++ks) {
            uint32_t bf[8];
#pragma unroll
            for (int p = 0; p < 2; ++p) {
                int rowB = warpN * 32 + p * 16 + ((lm >> 1) << 3) + r8;
                ldsm4(&bf[p * 4], stgB + sw_off(rowB, ks * 2 + (lm & 1)));
            }
#pragma unroll
            for (int mt = 0; mt < 4; ++mt) {
                int rowA = warpM * 64 + mt * 16 + ((lm & 1) << 3) + r8;
                uint32_t af[4];
                ldsm4(af, stgA + sw_off(rowA, ks * 2 + (lm >> 1)));
#pragma unroll
                for (int nt = 0; nt < 4; ++nt)
                    mma_f16(acc[mt][nt], af, &bf[nt * 2]);
            }
        }
    }

    int rr = lane >> 2;
    int q2 = (lane & 3) * 2;
#pragma unroll
    for (int mt = 0; mt < 4; ++mt) {
#pragma unroll
        for (int half = 0; half < 2; ++half) {
            int o = warpM * 64 + mt * 16 + rr + half * 8;
            float bias = pob[o];
            float* dst = out + (size_t)(b * 128 + o) * SPATIAL + s0;
#pragma unroll
            for (int nt = 0; nt < 4; ++nt) {
                int x = warpN * 32 + nt * 8 + q2;
                float v0 = acc[mt][nt][half * 2 + 0] + bias;
                float v1 = acc[mt][nt][half * 2 + 1] + bias;
                *(float2*)(dst + x) = make_float2(v0, v1);
            }
        }
    }
}

// ---------------------------------------------------------------------------
extern "C" void kernel_launch(void* const* d_in, const int* in_sizes, int n_in,
                              void* d_out, int out_size) {
    const float* x     = (const float*)d_in[0];
    const float* qkv_r = (const float*)d_in[1];
    const float* qkv_i = (const float*)d_in[2];
    const float* qkv_j = (const float*)d_in[3];
    const float* qkv_k = (const float*)d_in[4];
    const float* qkv_b = (const float*)d_in[5];
    const float* dw_r  = (const float*)d_in[6];
    const float* dw_i  = (const float*)d_in[7];
    const float* dw_j  = (const float*)d_in[8];
    const float* dw_k  = (const float*)d_in[9];
    const float* dw_b  = (const float*)d_in[10];
    const float* po_r  = (const float*)d_in[11];
    const float* po_i  = (const float*)d_in[12];
    const float* po_j  = (const float*)d_in[13];
    const float* po_k  = (const float*)d_in[14];
    const float* po_b  = (const float*)d_in[15];
    const float* temp  = (const float*)d_in[16];
    float* out = (float*)d_out;

    cudaFuncSetAttribute(conv_mma, cudaFuncAttributeMaxDynamicSharedMemorySize,
                         CONV_SMEM);
    cudaFuncSetAttribute(final_mma, cudaFuncAttributeMaxDynamicSharedMemorySize,
                         FG_SMEM);

    // 8 launches; conv is 4th (profiled slot)
    expand_all<<<(N_QKV + N_DW + N_PO + 255) / 256, 256>>>(
        qkv_r, qkv_i, qkv_j, qkv_k, dw_r, dw_i, dw_j, dw_k,
        po_r, po_i, po_j, po_k);
    weff_o<<<384, 128>>>(qkv_b);
    prep_x<<<dim3(512, 2), 256>>>(x);

    conv_mma<<<dim3(128, 3, 2), 256, CONV_SMEM>>>(dw_b);

    prep_v<<<dim3(512, 2), 256>>>();
    attn_partial<<<dim3(32, 8), 256>>>();
    softmax_M2<<<dim3(2, 4), 256>>>(temp);
    final_mma<<<dim3(128, 1, 2), 256, FG_SMEM>>>(po_b, out);
}

// round 13
// speedup vs baseline: 1.4654x; 1.0612x over previous
#include <cuda_runtime.h>
#include <cuda_fp16.h>
#include <cstdint>
#include <math.h>

// ---------------------------------------------------------------------------
// QAttention round 12:
//  - q,k intermediates stored fp16 (g_qkv2h); sumsq still fp32 pre-quantize.
//  - conv v-CTAs transpose v in smem and emit g_v16 [s][d] directly
//    (prep_v kernel deleted). Tail traffic 109MB -> ~42MB.
//  - attn_partial reads fp16.
// ---------------------------------------------------------------------------

#define SPATIAL 16384
typedef unsigned long long u64;

// ------------------------- mma.sync helpers --------------------------------
__device__ __forceinline__ uint32_t smem_to_u32(const void* p) {
    uint32_t a;
    asm("{ .reg .u64 t; cvta.to.shared.u64 t, %1; cvt.u32.u64 %0, t; }"
        : "=r"(a) : "l"(p));
    return a;
}
__device__ __forceinline__ void ldsm4(uint32_t* r, uint32_t addr) {
    asm volatile("ldmatrix.sync.aligned.m8n8.x4.shared.b16 {%0,%1,%2,%3}, [%4];"
                 : "=r"(r[0]), "=r"(r[1]), "=r"(r[2]), "=r"(r[3]) : "r"(addr));
}
__device__ __forceinline__ void mma_f16(float* d, const uint32_t* a,
                                        const uint32_t* b) {
    asm volatile(
        "mma.sync.aligned.m16n8k16.row.col.f32.f16.f16.f32 "
        "{%0,%1,%2,%3}, {%4,%5,%6,%7}, {%8,%9}, {%0,%1,%2,%3};"
        : "+f"(d[0]), "+f"(d[1]), "+f"(d[2]), "+f"(d[3])
        : "r"(a[0]), "r"(a[1]), "r"(a[2]), "r"(a[3]), "r"(b[0]), "r"(b[1]));
}
__device__ __forceinline__ uint32_t sw_off(int row, int unit) {
    return row * 128 + (((unit) ^ (row & 7)) << 4);
}
__device__ __forceinline__ void cp_async16(uint32_t saddr, const void* gptr,
                                           uint32_t bytes) {
    asm volatile("cp.async.cg.shared.global [%0], [%1], 16, %2;"
                 :: "r"(saddr), "l"(gptr), "r"(bytes) : "memory");
}
#define CP_COMMIT() asm volatile("cp.async.commit_group;" ::: "memory")
#define CP_WAIT1()  asm volatile("cp.async.wait_group 1;" ::: "memory")
#define CP_WAIT0()  asm volatile("cp.async.wait_group 0;" ::: "memory")

// ------------------------- device scratch ----------------------------------
__device__ float g_Wqkv[384 * 128];
__device__ float g_Wdw[384 * 384 * 9];
__device__ float g_Wpo[128 * 128];
__device__ __half g_Weff16[384 * 1152];          // [o][tap*128+c]
__device__ float g_tb[384 * 9];
__device__ __half g_xt16[2 * SPATIAL * 128];     // [b][s][c]
__device__ __half g_qkv2h[2 * 256 * SPATIAL];    // [b][qk ch][s] fp16
__device__ __half g_v16[2 * SPATIAL * 128];      // [b][s][d]
__device__ float g_attnP[2 * 4 * 32 * 32];
__device__ float g_ss[2 * 256];
__device__ __half g_M2h[2 * 128 * 128];          // fp16 po@attn

// ---------------------------------------------------------------------------
// P1: all three Hamilton expansions in one kernel.
// ---------------------------------------------------------------------------
__device__ __forceinline__ void ham_one(const float* r, const float* i_,
                                        const float* j_, const float* k_,
                                        float* dst, int idx,
                                        int O4, int C4, int T) {
    int tap = idx % T;
    int rem = idx / T;
    int C = 4 * C4;
    int c = rem % C;
    int o = rem / C;
    int br = o / O4, oo = o % O4;
    int bc = c / C4, cc = c % C4;

    const int   src[16] = {0,1,2,3, 1,0,3,2, 2,3,0,1, 3,2,1,0};
    const float sgn[16] = {1.f,-1.f,-1.f,-1.f, 1.f,1.f,-1.f,1.f,
                           1.f,1.f,1.f,-1.f,  1.f,-1.f,1.f,1.f};
    const float* comp[4] = {r, i_, j_, k_};
    dst[idx] = sgn[br * 4 + bc] * comp[src[br * 4 + bc]][(oo * C4 + cc) * T + tap];
}

#define N_QKV (384 * 128)
#define N_DW  (384 * 384 * 9)
#define N_PO  (128 * 128)

__global__ void expand_all(const float* __restrict__ qr, const float* __restrict__ qi,
                           const float* __restrict__ qj, const float* __restrict__ qk,
                           const float* __restrict__ dr, const float* __restrict__ di,
                           const float* __restrict__ dj, const float* __restrict__ dk,
                           const float* __restrict__ pr, const float* __restrict__ pi,
                           const float* __restrict__ pj, const float* __restrict__ pk) {
    int idx = blockIdx.x * 256 + threadIdx.x;
    if (idx < N_QKV) {
        ham_one(qr, qi, qj, qk, g_Wqkv, idx, 96, 32, 1);
    } else if (idx < N_QKV + N_DW) {
        ham_one(dr, di, dj, dk, g_Wdw, idx - N_QKV, 96, 96, 9);
    } else if (idx < N_QKV + N_DW + N_PO) {
        ham_one(pr, pi, pj, pk, g_Wpo, idx - N_QKV - N_DW, 32, 32, 1);
    }
}

// ---------------------------------------------------------------------------
// P2: Weff per output row -> fp16 at [o][tap*128+c]; tb fold.
// ---------------------------------------------------------------------------
__global__ __launch_bounds__(128)
void weff_o(const float* __restrict__ qkv_b) {
    int o = blockIdx.x;
    int c = threadIdx.x;

    __shared__ float wdw_s[288 + 8];
    __shared__ float wq_s[32 * 128];
    __shared__ float qb_s[384];

    for (int m = c; m < 384; m += 128) qb_s[m] = qkv_b[m];

    float acc[9], tbp[9];
#pragma unroll
    for (int t = 0; t < 9; ++t) { acc[t] = 0.f; tbp[t] = 0.f; }

    const float* wdw_row = g_Wdw + (size_t)o * 3456;

    for (int cb = 0; cb < 12; ++cb) {
        __syncthreads();
        for (int i = c; i < 288; i += 128)
            wdw_s[i] = wdw_row[cb * 288 + i];
        for (int i = c; i < 4096; i += 128) {
            int m = i >> 7, col = i & 127;
            wq_s[m * 128 + col] = g_Wqkv[(cb * 32 + m) * 128 + col];
        }
        __syncthreads();
#pragma unroll 4
        for (int m = 0; m < 32; ++m) {
            float wq = wq_s[m * 128 + c];
#pragma unroll
            for (int t = 0; t < 9; ++t)
                acc[t] = fmaf(wdw_s[m * 9 + t], wq, acc[t]);
        }
        if (c < 32) {
            float qb = qb_s[cb * 32 + c];
#pragma unroll
            for (int t = 0; t < 9; ++t)
                tbp[t] = fmaf(wdw_s[c * 9 + t], qb, tbp[t]);
        }
    }

#pragma unroll
    for (int t = 0; t < 9; ++t)
        g_Weff16[(size_t)o * 1152 + t * 128 + c] = __float2half(acc[t]);

    if (c < 32) {
#pragma unroll
        for (int t = 0; t < 9; ++t) {
            float v = tbp[t];
#pragma unroll
            for (int off = 16; off; off >>= 1)
                v += __shfl_xor_sync(0xffffffffu, v, off);
            if (c == 0) g_tb[o * 9 + t] = v;
        }
    }
}

// ---------------------------------------------------------------------------
// P3: transpose x to [b][s][c] fp16; block(0,0) also zeros scratch.
// ---------------------------------------------------------------------------
__global__ void prep_x(const float* __restrict__ X) {
    __shared__ float t[128][33];
    int s0 = blockIdx.x * 32;
    int b  = blockIdx.y;
    int tid = threadIdx.x;

    if (blockIdx.x == 0 && b == 0) {
        for (int i = tid; i < 8192; i += 256) g_attnP[i] = 0.f;
        for (int i = tid; i < 512; i += 256) g_ss[i] = 0.f;
    }
    for (int i = tid; i < 4096; i += 256) {
        int c = i >> 5, s = i & 31;
        t[c][s] = X[((size_t)(b * 128 + c)) * SPATIAL + s0 + s];
    }
    __syncthreads();
    for (int i = tid; i < 4096; i += 256) {
        int s = i >> 7, c = i & 127;
        g_xt16[((size_t)b * SPATIAL + s0 + s) * 128 + c] = __float2half(t[c][s]);
    }
}

// ---------------------------------------------------------------------------
// P4: conv via mma.sync fp16, 3-stage cp.async ring, invariant fill addresses.
// CTA = M128 x N128, 256 threads (8 warps 2Mx4N), warp tile 64x32.
// Epilogue: q,k tiles -> g_qkv2h fp16 + sumsq; v tile -> smem transpose ->
// g_v16 [s][d] fp16 directly.
// ---------------------------------------------------------------------------
#define ST_A 0
#define ST_B (16 * 1024)
#define STAGE_BYTES (32 * 1024)
#define CONV_SMEM (3 * STAGE_BYTES)
#define VT_STRIDE 136   // halves; 272B rows (16B aligned)

__global__ __launch_bounds__(256, 2)
void conv_mma(const float* __restrict__ dwb) {
    extern __shared__ char smem[];
    uint32_t sbase = smem_to_u32(smem);
    int tid = threadIdx.x, wid = tid >> 5, lane = tid & 31;
    int y  = blockIdx.x;          // image row
    int o0 = blockIdx.y * 128;    // output-channel tile
    int b  = blockIdx.z;

    int warpM = wid >> 2;         // 0..1 -> 64 chans
    int warpN = wid & 3;          // 0..3 -> 32 pixels
    int lm = lane >> 3;
    int r8 = lane & 7;

    // ---- invariant fill state ----
    int rowT = tid >> 3, uT = tid & 7;
    const __half* pA0 = g_Weff16 + (size_t)(o0 + rowT) * 1152 + uT * 8;
    const __half* pB0 = g_xt16 + ((size_t)b * SPATIAL + y * 128 + rowT) * 128 + uT * 8;
    uint32_t dA0 = ST_A + sw_off(rowT, uT);
    uint32_t dB0 = ST_B + sw_off(rowT, uT);
    uint32_t maskB[4];
#pragma unroll
    for (int j = 0; j < 4; ++j) {
        int n = rowT + 32 * j;
        uint32_t m = 0;
        for (int it = 0; it < 18; ++it) {
            int tap = it >> 1;
            int dy = tap / 3 - 1, dx = tap % 3 - 1;
            bool ok = ((unsigned)(y + dy) < 128u) && ((unsigned)(n + dx) < 128u);
            m |= (ok ? 1u : 0u) << it;
        }
        maskB[j] = m;
    }

    uint32_t offA[4][4], offB[4][2];
#pragma unroll
    for (int ks = 0; ks < 4; ++ks) {
#pragma unroll
        for (int mt = 0; mt < 4; ++mt) {
            int rowA = warpM * 64 + mt * 16 + ((lm & 1) << 3) + r8;
            offA[mt][ks] = ST_A + sw_off(rowA, ks * 2 + (lm >> 1));
        }
#pragma unroll
        for (int p = 0; p < 2; ++p) {
            int rowB = warpN * 32 + p * 16 + ((lm >> 1) << 3) + r8;
            offB[ks][p] = ST_B + sw_off(rowB, ks * 2 + (lm & 1));
        }
    }

    float acc[4][4][4];
#pragma unroll
    for (int mt = 0; mt < 4; ++mt)
#pragma unroll
        for (int nt = 0; nt < 4; ++nt)
#pragma unroll
            for (int q = 0; q < 4; ++q) acc[mt][nt][q] = 0.f;

    auto do_fill = [&](uint32_t stg, int it2) {
        int tap = it2 >> 1;
        int dy = tap / 3 - 1, dx = tap - (tap / 3) * 3 - 1;
        int goff = (dy * 128 + dx) * 128 + ((it2 & 1) << 6);
#pragma unroll
        for (int j = 0; j < 4; ++j)
            cp_async16(stg + dA0 + j * 4096, pA0 + it2 * 64 + j * 36864, 16u);
#pragma unroll
        for (int j = 0; j < 4; ++j) {
            uint32_t ok = (maskB[j] >> it2) & 1u;
            const __half* s = ok ? (pB0 + goff + j * 4096) : g_xt16;
            cp_async16(stg + dB0 + j * 4096, s, ok ? 16u : 0u);
        }
        CP_COMMIT();
    };

    do_fill(sbase, 0);
    do_fill(sbase + STAGE_BYTES, 1);

    uint32_t cs = 0, fs = 2 * STAGE_BYTES;
    for (int it = 0; it < 18; ++it) {
        if (it < 16) CP_WAIT1(); else CP_WAIT0();
        __syncthreads();
        if (it + 2 < 18) do_fill(sbase + fs, it + 2);

        uint32_t stg = sbase + cs;
#pragma unroll
        for (int ks = 0; ks < 4; ++ks) {
            uint32_t bf[8];
            ldsm4(&bf[0], stg + offB[ks][0]);
            ldsm4(&bf[4], stg + offB[ks][1]);
#pragma unroll
            for (int mt = 0; mt < 4; ++mt) {
                uint32_t af[4];
                ldsm4(af, stg + offA[mt][ks]);
#pragma unroll
                for (int nt = 0; nt < 4; ++nt)
                    mma_f16(acc[mt][nt], af, &bf[nt * 2]);
            }
        }
        cs += STAGE_BYTES; if (cs == 3 * STAGE_BYTES) cs = 0;
        fs += STAGE_BYTES; if (fs == 3 * STAGE_BYTES) fs = 0;
    }
    __syncthreads();

    // bias triples + (v path) transpose buffer in reused stage smem
    float* bias_s = (float*)smem;                 // [128][3] = 1.5KB
    __half* vt = (__half*)(smem + 2048);          // [128][VT_STRIDE] = 34.8KB
    if (tid < 128) {
        int o = o0 + tid;
        const float* t = &g_tb[o * 9];
        float f0 = (y >= 1) ? 1.f : 0.f;
        float f2 = (y <= 126) ? 1.f : 0.f;
        bias_s[tid * 3 + 0] = dwb[o] + f0 * t[1] + t[4] + f2 * t[7];
        bias_s[tid * 3 + 1] = f0 * t[0] + t[3] + f2 * t[6];
        bias_s[tid * 3 + 2] = f0 * t[2] + t[5] + f2 * t[8];
    }
    __syncthreads();

    int rr = lane >> 2;
    int q2 = (lane & 3) * 2;
    if (o0 < 256) {
        // q,k: write fp16 rows + fused sumsq (fp32 pre-quantize)
#pragma unroll
        for (int mt = 0; mt < 4; ++mt) {
#pragma unroll
            for (int half = 0; half < 2; ++half) {
                int o_loc = warpM * 64 + mt * 16 + rr + half * 8;
                int o = o0 + o_loc;
                float base = bias_s[o_loc * 3 + 0];
                float rs0  = bias_s[o_loc * 3 + 1];
                float rs2  = bias_s[o_loc * 3 + 2];
                float ss = 0.f;
                __half* dst = g_qkv2h + (size_t)(b * 256 + o) * SPATIAL + y * 128;
#pragma unroll
                for (int nt = 0; nt < 4; ++nt) {
                    int x = warpN * 32 + nt * 8 + q2;
                    float v0 = acc[mt][nt][half * 2 + 0] + base + rs2;
                    if (x >= 1) v0 += rs0;
                    float v1 = acc[mt][nt][half * 2 + 1] + base + rs0;
                    if (x + 1 <= 126) v1 += rs2;
                    *(__half2*)(dst + x) = __floats2half2_rn(v0, v1);
                    ss = fmaf(v0, v0, ss);
                    ss = fmaf(v1, v1, ss);
                }
                ss += __shfl_xor_sync(0xffffffffu, ss, 1);
                ss += __shfl_xor_sync(0xffffffffu, ss, 2);
                if ((lane & 3) == 0)
                    atomicAdd(&g_ss[b * 256 + o], ss);
            }
        }
    } else {
        // v: bias add, transpose through smem, write g_v16 [s][d]
#pragma unroll
        for (int mt = 0; mt < 4; ++mt) {
#pragma unroll
            for (int half = 0; half < 2; ++half) {
                int d = warpM * 64 + mt * 16 + rr + half * 8;   // local v chan
                float base = bias_s[d * 3 + 0];
                float rs0  = bias_s[d * 3 + 1];
                float rs2  = bias_s[d * 3 + 2];
#pragma unroll
                for (int nt = 0; nt < 4; ++nt) {
                    int x = warpN * 32 + nt * 8 + q2;
                    float v0 = acc[mt][nt][half * 2 + 0] + base + rs2;
                    if (x >= 1) v0 += rs0;
                    float v1 = acc[mt][nt][half * 2 + 1] + base + rs0;
                    if (x + 1 <= 126) v1 += rs2;
                    vt[x * VT_STRIDE + d]       = __float2half(v0);
                    vt[(x + 1) * VT_STRIDE + d] = __float2half(v1);
                }
            }
        }
        __syncthreads();
        for (int i = tid; i < 2048; i += 256) {
            int s_loc = i >> 4, dseg = (i & 15) * 8;
            uint4 vv = *(const uint4*)&vt[s_loc * VT_STRIDE + dseg];
            *(uint4*)&g_v16[((size_t)b * SPATIAL + y * 128 + s_loc) * 128 + dseg] = vv;
        }
    }
}

// ---------------------------------------------------------------------------
// P5: attn partial sums; fp16 reads, transposed k tile, float4 smem reads.
// ---------------------------------------------------------------------------
__global__ void attn_partial() {
    int slice = blockIdx.x;
    int bh = blockIdx.y;
    int b = bh >> 2, h = bh & 3;
    const __half* qb = g_qkv2h + (size_t)(b * 256 + h * 32) * SPATIAL;
    const __half* kb = g_qkv2h + (size_t)(b * 256 + 128 + h * 32) * SPATIAL;

    __shared__ float qs[32][68];
    __shared__ float kt[64][36];
    int tid = threadIdx.x;
    int c = tid >> 3;
    int d0 = (tid & 7) * 4;
    float acc[4] = {0.f, 0.f, 0.f, 0.f};

    for (int sub = 0; sub < 8; ++sub) {
        int s0 = slice * 512 + sub * 64;
        for (int i = tid; i < 1024; i += 256) {
            int cc = i >> 5, kk2 = (i & 31) * 2;
            float2 qf = __half22float2(*(const __half2*)(qb + (size_t)cc * SPATIAL + s0 + kk2));
            qs[cc][kk2] = qf.x; qs[cc][kk2 + 1] = qf.y;
            float2 kf = __half22float2(*(const __half2*)(kb + (size_t)cc * SPATIAL + s0 + kk2));
            kt[kk2][cc] = kf.x; kt[kk2 + 1][cc] = kf.y;
        }
        __syncthreads();
#pragma unroll 4
        for (int kk = 0; kk < 64; kk += 4) {
            float4 q = *(const float4*)&qs[c][kk];
#pragma unroll
            for (int e = 0; e < 4; ++e) {
                float qe = (&q.x)[e];
                float4 kv = *(const float4*)&kt[kk + e][d0];
                acc[0] = fmaf(qe, kv.x, acc[0]);
                acc[1] = fmaf(qe, kv.y, acc[1]);
                acc[2] = fmaf(qe, kv.z, acc[2]);
                acc[3] = fmaf(qe, kv.w, acc[3]);
            }
        }
        __syncthreads();
    }
#pragma unroll
    for (int j = 0; j < 4; ++j)
        atomicAdd(&g_attnP[(bh * 32 + c) * 32 + d0 + j], acc[j]);
}

// ---------------------------------------------------------------------------
// P6: fused norms + softmax + M2 per (b,h); M2 emitted in fp16.
// ---------------------------------------------------------------------------
__global__ void softmax_M2(const float* __restrict__ temp) {
    int b = blockIdx.x, h = blockIdx.y;
    int bh = b * 4 + h;
    int tid = threadIdx.x, wid = tid >> 5, lane = tid & 31;

    __shared__ float A[32][33];
    __shared__ float W[128][33];

    float tp = temp[h];
    float invk = 1.f / fmaxf(sqrtf(g_ss[b * 256 + 128 + h * 32 + lane]), 1e-12f);
    for (int c = wid; c < 32; c += 8) {
        float invq = 1.f / fmaxf(sqrtf(g_ss[b * 256 + h * 32 + c]), 1e-12f);
        float v = g_attnP[(bh * 32 + c) * 32 + lane] * invq * invk * tp;
        float mx = v;
#pragma unroll
        for (int off = 16; off; off >>= 1)
            mx = fmaxf(mx, __shfl_xor_sync(0xffffffffu, mx, off));
        float e = expf(v - mx);
        float s = e;
#pragma unroll
        for (int off = 16; off; off >>= 1)
            s += __shfl_xor_sync(0xffffffffu, s, off);
        A[c][lane] = e / s;
    }
    for (int i = tid; i < 4096; i += 256) {
        int o = i >> 5, c = i & 31;
        W[o][c] = g_Wpo[o * 128 + h * 32 + c];
    }
    __syncthreads();

    int o = tid >> 1;
    int d0 = (tid & 1) * 16;
#pragma unroll
    for (int dd = 0; dd < 16; ++dd) {
        int d = d0 + dd;
        float s = 0.f;
#pragma unroll
        for (int c = 0; c < 32; ++c)
            s = fmaf(W[o][c], A[c][d], s);
        g_M2h[b * 16384 + o * 128 + h * 32 + d] = __float2half(s);
    }
}

// ---------------------------------------------------------------------------
// P7: out = M2h @ v16 + po_b  via fp16 HMMA. CTA = M128 x N128, K=128.
// ---------------------------------------------------------------------------
#define FG_A 0
#define FG_B (32 * 1024)
#define FG_SMEM (64 * 1024)

__global__ __launch_bounds__(256)
void final_mma(const float* __restrict__ pob, float* __restrict__ out) {
    extern __shared__ char smem[];
    uint32_t sbase = smem_to_u32(smem);
    int tid = threadIdx.x, wid = tid >> 5, lane = tid & 31;
    int s0 = blockIdx.x * 128;
    int b  = blockIdx.z;

    int warpM = wid >> 2;
    int warpN = wid & 3;
    int lm = lane >> 3;
    int r8 = lane & 7;

    for (int i = tid; i < 2048; i += 256) {
        int kc = i >> 10, row = (i >> 3) & 127, u = i & 7;
        const __half* sa = g_M2h + (size_t)b * 16384 + row * 128 + kc * 64 + u * 8;
        cp_async16(sbase + FG_A + kc * 16384 + sw_off(row, u), sa, 16u);
        const __half* sb = g_v16 + ((size_t)b * SPATIAL + s0 + row) * 128 + kc * 64 + u * 8;
        cp_async16(sbase + FG_B + kc * 16384 + sw_off(row, u), sb, 16u);
    }
    CP_COMMIT();
    CP_WAIT0();
    __syncthreads();

    float acc[4][4][4];
#pragma unroll
    for (int mt = 0; mt < 4; ++mt)
#pragma unroll
        for (int nt = 0; nt < 4; ++nt)
#pragma unroll
            for (int q = 0; q < 4; ++q) acc[mt][nt][q] = 0.f;

#pragma unroll
    for (int kc = 0; kc < 2; ++kc) {
        uint32_t stgA = sbase + FG_A + kc * 16384;
        uint32_t stgB = sbase + FG_B + kc * 16384;
#pragma unroll
        for (int ks = 0; ks < 4; ++ks) {
            uint32_t bf[8];
#pragma unroll
            for (int p = 0; p < 2; ++p) {
                int rowB = warpN * 32 + p * 16 + ((lm >> 1) << 3) + r8;
                ldsm4(&bf[p * 4], stgB + sw_off(rowB, ks * 2 + (lm & 1)));
            }
#pragma unroll
            for (int mt = 0; mt < 4; ++mt) {
                int rowA = warpM * 64 + mt * 16 + ((lm & 1) << 3) + r8;
                uint32_t af[4];
                ldsm4(af, stgA + sw_off(rowA, ks * 2 + (lm >> 1)));
#pragma unroll
                for (int nt = 0; nt < 4; ++nt)
                    mma_f16(acc[mt][nt], af, &bf[nt * 2]);
            }
        }
    }

    int rr = lane >> 2;
    int q2 = (lane & 3) * 2;
#pragma unroll
    for (int mt = 0; mt < 4; ++mt) {
#pragma unroll
        for (int half = 0; half < 2; ++half) {
            int o = warpM * 64 + mt * 16 + rr + half * 8;
            float bias = pob[o];
            float* dst = out + (size_t)(b * 128 + o) * SPATIAL + s0;
#pragma unroll
            for (int nt = 0; nt < 4; ++nt) {
                int x = warpN * 32 + nt * 8 + q2;
                float v0 = acc[mt][nt][half * 2 + 0] + bias;
                float v1 = acc[mt][nt][half * 2 + 1] + bias;
                *(float2*)(dst + x) = make_float2(v0, v1);
            }
        }
    }
}

// ---------------------------------------------------------------------------
extern "C" void kernel_launch(void* const* d_in, const int* in_sizes, int n_in,
                              void* d_out, int out_size) {
    const float* x     = (const float*)d_in[0];
    const float* qkv_r = (const float*)d_in[1];
    const float* qkv_i = (const float*)d_in[2];
    const float* qkv_j = (const float*)d_in[3];
    const float* qkv_k = (const float*)d_in[4];
    const float* qkv_b = (const float*)d_in[5];
    const float* dw_r  = (const float*)d_in[6];
    const float* dw_i  = (const float*)d_in[7];
    const float* dw_j  = (const float*)d_in[8];
    const float* dw_k  = (const float*)d_in[9];
    const float* dw_b  = (const float*)d_in[10];
    const float* po_r  = (const float*)d_in[11];
    const float* po_i  = (const float*)d_in[12];
    const float* po_j  = (const float*)d_in[13];
    const float* po_k  = (const float*)d_in[14];
    const float* po_b  = (const float*)d_in[15];
    const float* temp  = (const float*)d_in[16];
    float* out = (float*)d_out;

    cudaFuncSetAttribute(conv_mma, cudaFuncAttributeMaxDynamicSharedMemorySize,
                         CONV_SMEM);
    cudaFuncSetAttribute(final_mma, cudaFuncAttributeMaxDynamicSharedMemorySize,
                         FG_SMEM);

    // 7 launches; conv is 4th (profiled slot)
    expand_all<<<(N_QKV + N_DW + N_PO + 255) / 256, 256>>>(
        qkv_r, qkv_i, qkv_j, qkv_k, dw_r, dw_i, dw_j, dw_k,
        po_r, po_i, po_j, po_k);
    weff_o<<<384, 128>>>(qkv_b);
    prep_x<<<dim3(512, 2), 256>>>(x);

    conv_mma<<<dim3(128, 3, 2), 256, CONV_SMEM>>>(dw_b);

    attn_partial<<<dim3(32, 8), 256>>>();
    softmax_M2<<<dim3(2, 4), 256>>>(temp);
    final_mma<<<dim3(128, 1, 2), 256, FG_SMEM>>>(po_b, out);
}

// round 14
// speedup vs baseline: 1.7856x; 1.2185x over previous
#include <cuda_runtime.h>
#include <cuda_fp16.h>
#include <cstdint>
#include <math.h>

// ---------------------------------------------------------------------------
// QAttention round 13:
//  - weff_o applies the Hamilton expansion of Wdw on the fly (g_Wdw and the
//    19MB expand+re-read round trip deleted; expand_small keeps qkv/po only).
//  - attn_partial -> attn_mma: fp16 HMMA with the conv's validated fragment
//    mapping (M=32,N=32, K-parallel warps, smem tree-reduce + atomics).
//  - conv unchanged (82.5us, tensor 57%).
// ---------------------------------------------------------------------------

#define SPATIAL 16384
typedef unsigned long long u64;

// ------------------------- mma.sync helpers --------------------------------
__device__ __forceinline__ uint32_t smem_to_u32(const void* p) {
    uint32_t a;
    asm("{ .reg .u64 t; cvta.to.shared.u64 t, %1; cvt.u32.u64 %0, t; }"
        : "=r"(a) : "l"(p));
    return a;
}
__device__ __forceinline__ void ldsm4(uint32_t* r, uint32_t addr) {
    asm volatile("ldmatrix.sync.aligned.m8n8.x4.shared.b16 {%0,%1,%2,%3}, [%4];"
                 : "=r"(r[0]), "=r"(r[1]), "=r"(r[2]), "=r"(r[3]) : "r"(addr));
}
__device__ __forceinline__ void mma_f16(float* d, const uint32_t* a,
                                        const uint32_t* b) {
    asm volatile(
        "mma.sync.aligned.m16n8k16.row.col.f32.f16.f16.f32 "
        "{%0,%1,%2,%3}, {%4,%5,%6,%7}, {%8,%9}, {%0,%1,%2,%3};"
        : "+f"(d[0]), "+f"(d[1]), "+f"(d[2]), "+f"(d[3])
        : "r"(a[0]), "r"(a[1]), "r"(a[2]), "r"(a[3]), "r"(b[0]), "r"(b[1]));
}
__device__ __forceinline__ uint32_t sw_off(int row, int unit) {
    return row * 128 + (((unit) ^ (row & 7)) << 4);
}
__device__ __forceinline__ void cp_async16(uint32_t saddr, const void* gptr,
                                           uint32_t bytes) {
    asm volatile("cp.async.cg.shared.global [%0], [%1], 16, %2;"
                 :: "r"(saddr), "l"(gptr), "r"(bytes) : "memory");
}
#define CP_COMMIT() asm volatile("cp.async.commit_group;" ::: "memory")
#define CP_WAIT1()  asm volatile("cp.async.wait_group 1;" ::: "memory")
#define CP_WAIT0()  asm volatile("cp.async.wait_group 0;" ::: "memory")

// ------------------------- device scratch ----------------------------------
__device__ float g_Wqkv[384 * 128];
__device__ float g_Wpo[128 * 128];
__device__ __half g_Weff16[384 * 1152];          // [o][tap*128+c]
__device__ float g_tb[384 * 9];
__device__ __half g_xt16[2 * SPATIAL * 128];     // [b][s][c]
__device__ __half g_qkv2h[2 * 256 * SPATIAL];    // [b][qk ch][s] fp16
__device__ __half g_v16[2 * SPATIAL * 128];      // [b][s][d]
__device__ float g_attnP[2 * 4 * 32 * 32];
__device__ float g_ss[2 * 256];
__device__ __half g_M2h[2 * 128 * 128];          // fp16 po@attn

// Hamilton tables (constant memory)
__constant__ int   c_src[16] = {0,1,2,3, 1,0,3,2, 2,3,0,1, 3,2,1,0};
__constant__ float c_sgn[16] = {1.f,-1.f,-1.f,-1.f, 1.f,1.f,-1.f,1.f,
                                1.f,1.f,1.f,-1.f,  1.f,-1.f,1.f,1.f};

// ---------------------------------------------------------------------------
// P1: Hamilton expansion for qkv (384x128) and po (128x128) only.
// ---------------------------------------------------------------------------
#define N_QKV (384 * 128)
#define N_PO  (128 * 128)

__global__ void expand_small(const float* __restrict__ qr, const float* __restrict__ qi,
                             const float* __restrict__ qj, const float* __restrict__ qk,
                             const float* __restrict__ pr, const float* __restrict__ pi,
                             const float* __restrict__ pj, const float* __restrict__ pk) {
    int idx = blockIdx.x * 256 + threadIdx.x;
    if (idx < N_QKV) {
        int c = idx & 127, o = idx >> 7;
        int br = o / 96, oo = o % 96;
        int bc = c >> 5, cc = c & 31;
        const float* comp[4] = {qr, qi, qj, qk};
        g_Wqkv[idx] = c_sgn[br * 4 + bc] * comp[c_src[br * 4 + bc]][oo * 32 + cc];
    } else if (idx < N_QKV + N_PO) {
        int j = idx - N_QKV;
        int c = j & 127, o = j >> 7;
        int br = o >> 5, oo = o & 31;
        int bc = c >> 5, cc = c & 31;
        const float* comp[4] = {pr, pi, pj, pk};
        g_Wpo[j] = c_sgn[br * 4 + bc] * comp[c_src[br * 4 + bc]][oo * 32 + cc];
    }
}

// ---------------------------------------------------------------------------
// P2: Weff per output row, Hamilton-on-the-fly Wdw loads; tb fold.
// ---------------------------------------------------------------------------
__global__ __launch_bounds__(128)
void weff_o(const float* __restrict__ qkv_b,
            const float* __restrict__ dr, const float* __restrict__ di,
            const float* __restrict__ dj, const float* __restrict__ dk) {
    int o = blockIdx.x;
    int c = threadIdx.x;
    int br = o / 96, oo = o % 96;

    __shared__ float wdw_s[288 + 8];
    __shared__ float wq_s[32 * 128];
    __shared__ float qb_s[384];
    __shared__ const float* comp_s[4];
    __shared__ float sgn_s[4];

    if (c == 0) {
        const float* comp[4] = {dr, di, dj, dk};
#pragma unroll
        for (int bc = 0; bc < 4; ++bc) {
            comp_s[bc] = comp[c_src[br * 4 + bc]];
            sgn_s[bc] = c_sgn[br * 4 + bc];
        }
    }
    for (int m = c; m < 384; m += 128) qb_s[m] = qkv_b[m];

    float acc[9], tbp[9];
#pragma unroll
    for (int t = 0; t < 9; ++t) { acc[t] = 0.f; tbp[t] = 0.f; }

    for (int cb = 0; cb < 12; ++cb) {
        __syncthreads();
        for (int i = c; i < 288; i += 128) {
            int mi = i / 9, tap = i - mi * 9;
            int m = cb * 32 + mi;
            int bc = m / 96, cc = m - bc * 96;
            wdw_s[i] = sgn_s[bc] * comp_s[bc][(oo * 96 + cc) * 9 + tap];
        }
        for (int i = c; i < 4096; i += 128) {
            int m = i >> 7, col = i & 127;
            wq_s[m * 128 + col] = g_Wqkv[(cb * 32 + m) * 128 + col];
        }
        __syncthreads();
#pragma unroll 4
        for (int m = 0; m < 32; ++m) {
            float wq = wq_s[m * 128 + c];
#pragma unroll
            for (int t = 0; t < 9; ++t)
                acc[t] = fmaf(wdw_s[m * 9 + t], wq, acc[t]);
        }
        if (c < 32) {
            float qb = qb_s[cb * 32 + c];
#pragma unroll
            for (int t = 0; t < 9; ++t)
                tbp[t] = fmaf(wdw_s[c * 9 + t], qb, tbp[t]);
        }
    }

#pragma unroll
    for (int t = 0; t < 9; ++t)
        g_Weff16[(size_t)o * 1152 + t * 128 + c] = __float2half(acc[t]);

    if (c < 32) {
#pragma unroll
        for (int t = 0; t < 9; ++t) {
            float v = tbp[t];
#pragma unroll
            for (int off = 16; off; off >>= 1)
                v += __shfl_xor_sync(0xffffffffu, v, off);
            if (c == 0) g_tb[o * 9 + t] = v;
        }
    }
}

// ---------------------------------------------------------------------------
// P3: transpose x to [b][s][c] fp16; block(0,0) also zeros scratch.
// ---------------------------------------------------------------------------
__global__ void prep_x(const float* __restrict__ X) {
    __shared__ float t[128][33];
    int s0 = blockIdx.x * 32;
    int b  = blockIdx.y;
    int tid = threadIdx.x;

    if (blockIdx.x == 0 && b == 0) {
        for (int i = tid; i < 8192; i += 256) g_attnP[i] = 0.f;
        for (int i = tid; i < 512; i += 256) g_ss[i] = 0.f;
    }
    for (int i = tid; i < 4096; i += 256) {
        int c = i >> 5, s = i & 31;
        t[c][s] = X[((size_t)(b * 128 + c)) * SPATIAL + s0 + s];
    }
    __syncthreads();
    for (int i = tid; i < 4096; i += 256) {
        int s = i >> 7, c = i & 127;
        g_xt16[((size_t)b * SPATIAL + s0 + s) * 128 + c] = __float2half(t[c][s]);
    }
}

// ---------------------------------------------------------------------------
// P4: conv via mma.sync fp16, 3-stage cp.async ring (unchanged from r12).
// ---------------------------------------------------------------------------
#define ST_A 0
#define ST_B (16 * 1024)
#define STAGE_BYTES (32 * 1024)
#define CONV_SMEM (3 * STAGE_BYTES)
#define VT_STRIDE 136

__global__ __launch_bounds__(256, 2)
void conv_mma(const float* __restrict__ dwb) {
    extern __shared__ char smem[];
    uint32_t sbase = smem_to_u32(smem);
    int tid = threadIdx.x, wid = tid >> 5, lane = tid & 31;
    int y  = blockIdx.x;
    int o0 = blockIdx.y * 128;
    int b  = blockIdx.z;

    int warpM = wid >> 2;
    int warpN = wid & 3;
    int lm = lane >> 3;
    int r8 = lane & 7;

    int rowT = tid >> 3, uT = tid & 7;
    const __half* pA0 = g_Weff16 + (size_t)(o0 + rowT) * 1152 + uT * 8;
    const __half* pB0 = g_xt16 + ((size_t)b * SPATIAL + y * 128 + rowT) * 128 + uT * 8;
    uint32_t dA0 = ST_A + sw_off(rowT, uT);
    uint32_t dB0 = ST_B + sw_off(rowT, uT);
    uint32_t maskB[4];
#pragma unroll
    for (int j = 0; j < 4; ++j) {
        int n = rowT + 32 * j;
        uint32_t m = 0;
        for (int it = 0; it < 18; ++it) {
            int tap = it >> 1;
            int dy = tap / 3 - 1, dx = tap % 3 - 1;
            bool ok = ((unsigned)(y + dy) < 128u) && ((unsigned)(n + dx) < 128u);
            m |= (ok ? 1u : 0u) << it;
        }
        maskB[j] = m;
    }

    uint32_t offA[4][4], offB[4][2];
#pragma unroll
    for (int ks = 0; ks < 4; ++ks) {
#pragma unroll
        for (int mt = 0; mt < 4; ++mt) {
            int rowA = warpM * 64 + mt * 16 + ((lm & 1) << 3) + r8;
            offA[mt][ks] = ST_A + sw_off(rowA, ks * 2 + (lm >> 1));
        }
#pragma unroll
        for (int p = 0; p < 2; ++p) {
            int rowB = warpN * 32 + p * 16 + ((lm >> 1) << 3) + r8;
            offB[ks][p] = ST_B + sw_off(rowB, ks * 2 + (lm & 1));
        }
    }

    float acc[4][4][4];
#pragma unroll
    for (int mt = 0; mt < 4; ++mt)
#pragma unroll
        for (int nt = 0; nt < 4; ++nt)
#pragma unroll
            for (int q = 0; q < 4; ++q) acc[mt][nt][q] = 0.f;

    auto do_fill = [&](uint32_t stg, int it2) {
        int tap = it2 >> 1;
        int dy = tap / 3 - 1, dx = tap - (tap / 3) * 3 - 1;
        int goff = (dy * 128 + dx) * 128 + ((it2 & 1) << 6);
#pragma unroll
        for (int j = 0; j < 4; ++j)
            cp_async16(stg + dA0 + j * 4096, pA0 + it2 * 64 + j * 36864, 16u);
#pragma unroll
        for (int j = 0; j < 4; ++j) {
            uint32_t ok = (maskB[j] >> it2) & 1u;
            const __half* s = ok ? (pB0 + goff + j * 4096) : g_xt16;
            cp_async16(stg + dB0 + j * 4096, s, ok ? 16u : 0u);
        }
        CP_COMMIT();
    };

    do_fill(sbase, 0);
    do_fill(sbase + STAGE_BYTES, 1);

    uint32_t cs = 0, fs = 2 * STAGE_BYTES;
    for (int it = 0; it < 18; ++it) {
        if (it < 16) CP_WAIT1(); else CP_WAIT0();
        __syncthreads();
        if (it + 2 < 18) do_fill(sbase + fs, it + 2);

        uint32_t stg = sbase + cs;
#pragma unroll
        for (int ks = 0; ks < 4; ++ks) {
            uint32_t bf[8];
            ldsm4(&bf[0], stg + offB[ks][0]);
            ldsm4(&bf[4], stg + offB[ks][1]);
#pragma unroll
            for (int mt = 0; mt < 4; ++mt) {
                uint32_t af[4];
                ldsm4(af, stg + offA[mt][ks]);
#pragma unroll
                for (int nt = 0; nt < 4; ++nt)
                    mma_f16(acc[mt][nt], af, &bf[nt * 2]);
            }
        }
        cs += STAGE_BYTES; if (cs == 3 * STAGE_BYTES) cs = 0;
        fs += STAGE_BYTES; if (fs == 3 * STAGE_BYTES) fs = 0;
    }
    __syncthreads();

    float* bias_s = (float*)smem;
    __half* vt = (__half*)(smem + 2048);
    if (tid < 128) {
        int o = o0 + tid;
        const float* t = &g_tb[o * 9];
        float f0 = (y >= 1) ? 1.f : 0.f;
        float f2 = (y <= 126) ? 1.f : 0.f;
        bias_s[tid * 3 + 0] = dwb[o] + f0 * t[1] + t[4] + f2 * t[7];
        bias_s[tid * 3 + 1] = f0 * t[0] + t[3] + f2 * t[6];
        bias_s[tid * 3 + 2] = f0 * t[2] + t[5] + f2 * t[8];
    }
    __syncthreads();

    int rr = lane >> 2;
    int q2 = (lane & 3) * 2;
    if (o0 < 256) {
#pragma unroll
        for (int mt = 0; mt < 4; ++mt) {
#pragma unroll
            for (int half = 0; half < 2; ++half) {
                int o_loc = warpM * 64 + mt * 16 + rr + half * 8;
                int o = o0 + o_loc;
                float base = bias_s[o_loc * 3 + 0];
                float rs0  = bias_s[o_loc * 3 + 1];
                float rs2  = bias_s[o_loc * 3 + 2];
                float ss = 0.f;
                __half* dst = g_qkv2h + (size_t)(b * 256 + o) * SPATIAL + y * 128;
#pragma unroll
                for (int nt = 0; nt < 4; ++nt) {
                    int x = warpN * 32 + nt * 8 + q2;
                    float v0 = acc[mt][nt][half * 2 + 0] + base + rs2;
                    if (x >= 1) v0 += rs0;
                    float v1 = acc[mt][nt][half * 2 + 1] + base + rs0;
                    if (x + 1 <= 126) v1 += rs2;
                    *(__half2*)(dst + x) = __floats2half2_rn(v0, v1);
                    ss = fmaf(v0, v0, ss);
                    ss = fmaf(v1, v1, ss);
                }
                ss += __shfl_xor_sync(0xffffffffu, ss, 1);
                ss += __shfl_xor_sync(0xffffffffu, ss, 2);
                if ((lane & 3) == 0)
                    atomicAdd(&g_ss[b * 256 + o], ss);
            }
        }
    } else {
#pragma unroll
        for (int mt = 0; mt < 4; ++mt) {
#pragma unroll
            for (int half = 0; half < 2; ++half) {
                int d = warpM * 64 + mt * 16 + rr + half * 8;
                float base = bias_s[d * 3 + 0];
                float rs0  = bias_s[d * 3 + 1];
                float rs2  = bias_s[d * 3 + 2];
#pragma unroll
                for (int nt = 0; nt < 4; ++nt) {
                    int x = warpN * 32 + nt * 8 + q2;
                    float v0 = acc[mt][nt][half * 2 + 0] + base + rs2;
                    if (x >= 1) v0 += rs0;
                    float v1 = acc[mt][nt][half * 2 + 1] + base + rs0;
                    if (x + 1 <= 126) v1 += rs2;
                    vt[x * VT_STRIDE + d]       = __float2half(v0);
                    vt[(x + 1) * VT_STRIDE + d] = __float2half(v1);
                }
            }
        }
        __syncthreads();
        for (int i = tid; i < 2048; i += 256) {
            int s_loc = i >> 4, dseg = (i & 15) * 8;
            uint4 vv = *(const uint4*)&vt[s_loc * VT_STRIDE + dseg];
            *(uint4*)&g_v16[((size_t)b * SPATIAL + y * 128 + s_loc) * 128 + dseg] = vv;
        }
    }
}

// ---------------------------------------------------------------------------
// P5: attn logits via fp16 HMMA. Grid (16 slices, 8 bh), 256 thr (8 warps).
// Warp w handles k-range [slice*1024 + w*128, +128); per-warp private tiles
// q[32][64] / k[32][64] (8KB/warp, 64KB total); smem tree-reduce + atomics.
// ---------------------------------------------------------------------------
#define AT_SMEM (64 * 1024)

__global__ __launch_bounds__(256)
void attn_mma() {
    extern __shared__ char smem[];
    uint32_t sbase = smem_to_u32(smem);
    int tid = threadIdx.x, wid = tid >> 5, lane = tid & 31;
    int slice = blockIdx.x;
    int bh = blockIdx.y;
    int b = bh >> 2, h = bh & 3;
    const __half* qb = g_qkv2h + (size_t)(b * 256 + h * 32) * SPATIAL;
    const __half* kb = g_qkv2h + (size_t)(b * 256 + 128 + h * 32) * SPATIAL;

    uint32_t qts = sbase + wid * 8192;
    uint32_t kts = qts + 4096;
    int k0 = slice * 1024 + wid * 128;

    int lm = lane >> 3, r8 = lane & 7;
    uint32_t offA[2][4], offB[4][2];
#pragma unroll
    for (int ks = 0; ks < 4; ++ks) {
#pragma unroll
        for (int mt = 0; mt < 2; ++mt) {
            int rowA = mt * 16 + ((lm & 1) << 3) + r8;
            offA[mt][ks] = sw_off(rowA, ks * 2 + (lm >> 1));
        }
#pragma unroll
        for (int p = 0; p < 2; ++p) {
            int rowB = p * 16 + ((lm >> 1) << 3) + r8;
            offB[ks][p] = sw_off(rowB, ks * 2 + (lm & 1));
        }
    }

    float acc[2][4][4];
#pragma unroll
    for (int mt = 0; mt < 2; ++mt)
#pragma unroll
        for (int nt = 0; nt < 4; ++nt)
#pragma unroll
            for (int q = 0; q < 4; ++q) acc[mt][nt][q] = 0.f;

    for (int j = 0; j < 2; ++j) {
        int kk0 = k0 + j * 64;
        for (int t = lane; t < 256; t += 32) {
            int row = t >> 3, u = t & 7;
            cp_async16(qts + sw_off(row, u), qb + (size_t)row * SPATIAL + kk0 + u * 8, 16u);
            cp_async16(kts + sw_off(row, u), kb + (size_t)row * SPATIAL + kk0 + u * 8, 16u);
        }
        CP_COMMIT();
        CP_WAIT0();
        __syncthreads();
#pragma unroll
        for (int ks = 0; ks < 4; ++ks) {
            uint32_t bf[8];
            ldsm4(&bf[0], kts + offB[ks][0]);
            ldsm4(&bf[4], kts + offB[ks][1]);
#pragma unroll
            for (int mt = 0; mt < 2; ++mt) {
                uint32_t af[4];
                ldsm4(af, qts + offA[mt][ks]);
#pragma unroll
                for (int nt = 0; nt < 4; ++nt)
                    mma_f16(acc[mt][nt], af, &bf[nt * 2]);
            }
        }
        __syncthreads();
    }

    // tree reduce across warps via smem (reuse tile space)
    float* sred = (float*)smem;         // [8][32][36]
    int rr = lane >> 2, q2 = (lane & 3) * 2;
#pragma unroll
    for (int mt = 0; mt < 2; ++mt) {
#pragma unroll
        for (int half = 0; half < 2; ++half) {
            int m = mt * 16 + rr + half * 8;
#pragma unroll
            for (int nt = 0; nt < 4; ++nt) {
                int n = nt * 8 + q2;
                sred[(wid * 32 + m) * 36 + n]     = acc[mt][nt][half * 2 + 0];
                sred[(wid * 32 + m) * 36 + n + 1] = acc[mt][nt][half * 2 + 1];
            }
        }
    }
    __syncthreads();
    for (int i = tid; i < 1024; i += 256) {
        int m = i >> 5, n = i & 31;
        float s = 0.f;
#pragma unroll
        for (int w = 0; w < 8; ++w)
            s += sred[(w * 32 + m) * 36 + n];
        atomicAdd(&g_attnP[(bh * 32 + m) * 32 + n], s);
    }
}

// ---------------------------------------------------------------------------
// P6: fused norms + softmax + M2 per (b,h); M2 emitted in fp16.
// ---------------------------------------------------------------------------
__global__ void softmax_M2(const float* __restrict__ temp) {
    int b = blockIdx.x, h = blockIdx.y;
    int bh = b * 4 + h;
    int tid = threadIdx.x, wid = tid >> 5, lane = tid & 31;

    __shared__ float A[32][33];
    __shared__ float W[128][33];

    float tp = temp[h];
    float invk = 1.f / fmaxf(sqrtf(g_ss[b * 256 + 128 + h * 32 + lane]), 1e-12f);
    for (int c = wid; c < 32; c += 8) {
        float invq = 1.f / fmaxf(sqrtf(g_ss[b * 256 + h * 32 + c]), 1e-12f);
        float v = g_attnP[(bh * 32 + c) * 32 + lane] * invq * invk * tp;
        float mx = v;
#pragma unroll
        for (int off = 16; off; off >>= 1)
            mx = fmaxf(mx, __shfl_xor_sync(0xffffffffu, mx, off));
        float e = expf(v - mx);
        float s = e;
#pragma unroll
        for (int off = 16; off; off >>= 1)
            s += __shfl_xor_sync(0xffffffffu, s, off);
        A[c][lane] = e / s;
    }
    for (int i = tid; i < 4096; i += 256) {
        int o = i >> 5, c = i & 31;
        W[o][c] = g_Wpo[o * 128 + h * 32 + c];
    }
    __syncthreads();

    int o = tid >> 1;
    int d0 = (tid & 1) * 16;
#pragma unroll
    for (int dd = 0; dd < 16; ++dd) {
        int d = d0 + dd;
        float s = 0.f;
#pragma unroll
        for (int c = 0; c < 32; ++c)
            s = fmaf(W[o][c], A[c][d], s);
        g_M2h[b * 16384 + o * 128 + h * 32 + d] = __float2half(s);
    }
}

// ---------------------------------------------------------------------------
// P7: out = M2h @ v16 + po_b  via fp16 HMMA. CTA = M128 x N128, K=128.
// ---------------------------------------------------------------------------
#define FG_A 0
#define FG_B (32 * 1024)
#define FG_SMEM (64 * 1024)

__global__ __launch_bounds__(256)
void final_mma(const float* __restrict__ pob, float* __restrict__ out) {
    extern __shared__ char smem[];
    uint32_t sbase = smem_to_u32(smem);
    int tid = threadIdx.x, wid = tid >> 5, lane = tid & 31;
    int s0 = blockIdx.x * 128;
    int b  = blockIdx.z;

    int warpM = wid >> 2;
    int warpN = wid & 3;
    int lm = lane >> 3;
    int r8 = lane & 7;

    for (int i = tid; i < 2048; i += 256) {
        int kc = i >> 10, row = (i >> 3) & 127, u = i & 7;
        const __half* sa = g_M2h + (size_t)b * 16384 + row * 128 + kc * 64 + u * 8;
        cp_async16(sbase + FG_A + kc * 16384 + sw_off(row, u), sa, 16u);
        const __half* sb = g_v16 + ((size_t)b * SPATIAL + s0 + row) * 128 + kc * 64 + u * 8;
        cp_async16(sbase + FG_B + kc * 16384 + sw_off(row, u), sb, 16u);
    }
    CP_COMMIT();
    CP_WAIT0();
    __syncthreads();

    float acc[4][4][4];
#pragma unroll
    for (int mt = 0; mt < 4; ++mt)
#pragma unroll
        for (int nt = 0; nt < 4; ++nt)
#pragma unroll
            for (int q = 0; q < 4; ++q) acc[mt][nt][q] = 0.f;

#pragma unroll
    for (int kc = 0; kc < 2; ++kc) {
        uint32_t stgA = sbase + FG_A + kc * 16384;
        uint32_t stgB = sbase + FG_B + kc * 16384;
#pragma unroll
        for (int ks = 0; ks < 4; ++ks) {
            uint32_t bf[8];
#pragma unroll
            for (int p = 0; p < 2; ++p) {
                int rowB = warpN * 32 + p * 16 + ((lm >> 1) << 3) + r8;
                ldsm4(&bf[p * 4], stgB + sw_off(rowB, ks * 2 + (lm & 1)));
            }
#pragma unroll
            for (int mt = 0; mt < 4; ++mt) {
                int rowA = warpM * 64 + mt * 16 + ((lm & 1) << 3) + r8;
                uint32_t af[4];
                ldsm4(af, stgA + sw_off(rowA, ks * 2 + (lm >> 1)));
#pragma unroll
                for (int nt = 0; nt < 4; ++nt)
                    mma_f16(acc[mt][nt], af, &bf[nt * 2]);
            }
        }
    }

    int rr = lane >> 2;
    int q2 = (lane & 3) * 2;
#pragma unroll
    for (int mt = 0; mt < 4; ++mt) {
#pragma unroll
        for (int half = 0; half < 2; ++half) {
            int o = warpM * 64 + mt * 16 + rr + half * 8;
            float bias = pob[o];
            float* dst = out + (size_t)(b * 128 + o) * SPATIAL + s0;
#pragma unroll
            for (int nt = 0; nt < 4; ++nt) {
                int x = warpN * 32 + nt * 8 + q2;
                float v0 = acc[mt][nt][half * 2 + 0] + bias;
                float v1 = acc[mt][nt][half * 2 + 1] + bias;
                *(float2*)(dst + x) = make_float2(v0, v1);
            }
        }
    }
}

// ---------------------------------------------------------------------------
extern "C" void kernel_launch(void* const* d_in, const int* in_sizes, int n_in,
                              void* d_out, int out_size) {
    const float* x     = (const float*)d_in[0];
    const float* qkv_r = (const float*)d_in[1];
    const float* qkv_i = (const float*)d_in[2];
    const float* qkv_j = (const float*)d_in[3];
    const float* qkv_k = (const float*)d_in[4];
    const float* qkv_b = (const float*)d_in[5];
    const float* dw_r  = (const float*)d_in[6];
    const float* dw_i  = (const float*)d_in[7];
    const float* dw_j  = (const float*)d_in[8];
    const float* dw_k  = (const float*)d_in[9];
    const float* dw_b  = (const float*)d_in[10];
    const float* po_r  = (const float*)d_in[11];
    const float* po_i  = (const float*)d_in[12];
    const float* po_j  = (const float*)d_in[13];
    const float* po_k  = (const float*)d_in[14];
    const float* po_b  = (const float*)d_in[15];
    const float* temp  = (const float*)d_in[16];
    float* out = (float*)d_out;

    cudaFuncSetAttribute(conv_mma, cudaFuncAttributeMaxDynamicSharedMemorySize,
                         CONV_SMEM);
    cudaFuncSetAttribute(attn_mma, cudaFuncAttributeMaxDynamicSharedMemorySize,
                         AT_SMEM);
    cudaFuncSetAttribute(final_mma, cudaFuncAttributeMaxDynamicSharedMemorySize,
                         FG_SMEM);

    // 7 launches; conv is 4th (profiled slot)
    expand_small<<<(N_QKV + N_PO + 255) / 256, 256>>>(
        qkv_r, qkv_i, qkv_j, qkv_k, po_r, po_i, po_j, po_k);
    prep_x<<<dim3(512, 2), 256>>>(x);
    weff_o<<<384, 128>>>(qkv_b, dw_r, dw_i, dw_j, dw_k);

    conv_mma<<<dim3(128, 3, 2), 256, CONV_SMEM>>>(dw_b);

    attn_mma<<<dim3(16, 8), 256, AT_SMEM>>>();
    softmax_M2<<<dim3(2, 4), 256>>>(temp);
    final_mma<<<dim3(128, 1, 2), 256, FG_SMEM>>>(po_b, out);
}